// round 7
// baseline (speedup 1.0000x reference)
#include <cuda_runtime.h>
#include <cuda_bf16.h>
#include <math.h>

#define B_  64
#define S_  196
#define D_  2048
#define H_  8
#define DK_ 256
#define M_  16384
#define KSEL 32
#define C_  29

__device__ float g_xm [B_ * D_];
__device__ float g_t  [B_ * H_ * D_];
__device__ float g_u  [B_ * H_ * D_];
__device__ float g_sc [B_ * H_ * M_];
__device__ float g_z  [B_ * H_ * D_];
__device__ float g_fin[B_ * 2 * D_];
__device__ float g_fus[B_ * D_];
__device__ float g_part[4 * 512 * 2048];   // 16 MB scratch, region-multiplexed
__device__ float g_wkT [D_ * D_];
__device__ float g_mpwT[D_ * D_];

#define PART0 0
#define PART1 (1024 * 1024)      // +4 MB (in floats)
#define PART2 (2 * 1024 * 1024)  // +8 MB

__device__ __forceinline__ float gelu_exact(float v) {
    return 0.5f * v * (1.0f + erff(v * 0.70710678118654752f));
}
__device__ __forceinline__ void split2(float a, float b, unsigned& hi, unsigned& lo) {
    __nv_bfloat162 h = __floats2bfloat162_rn(a, b);
    __nv_bfloat162 l = __floats2bfloat162_rn(a - __bfloat162float(h.x),
                                             b - __bfloat162float(h.y));
    hi = *(unsigned*)&h; lo = *(unsigned*)&l;
}

#define LDSM4(R, ADDR) asm volatile( \
    "ldmatrix.sync.aligned.m8n8.x4.shared.b16 {%0,%1,%2,%3}, [%4];" \
    : "=r"((R)[0]), "=r"((R)[1]), "=r"((R)[2]), "=r"((R)[3]) : "r"(ADDR))
#define MMA16816(D, A, B0, B1) asm volatile( \
    "mma.sync.aligned.m16n8k16.row.col.f32.bf16.bf16.f32 " \
    "{%0,%1,%2,%3},{%4,%5,%6,%7},{%8,%9},{%0,%1,%2,%3};" \
    : "+f"((D)[0]), "+f"((D)[1]), "+f"((D)[2]), "+f"((D)[3]) \
    : "r"((A)[0]), "r"((A)[1]), "r"((A)[2]), "r"((A)[3]), "r"(B0), "r"(B1))

// ---------------- transpose fp32 DxD ----------------
__global__ void transpose_kernel(const float* __restrict__ in, float* __restrict__ out) {
    __shared__ float tile[32][33];
    int x = blockIdx.x * 32 + threadIdx.x;
    #pragma unroll
    for (int j = threadIdx.y; j < 32; j += 8)
        tile[j][threadIdx.x] = __ldcs(&in[(size_t)(blockIdx.y * 32 + j) * D_ + x]);
    __syncthreads();
    int xo = blockIdx.y * 32 + threadIdx.x;
    #pragma unroll
    for (int j = threadIdx.y; j < 32; j += 8)
        out[(size_t)(blockIdx.x * 32 + j) * D_ + xo] = tile[threadIdx.x][j];
}

// ---------------- mean over S: two phase ----------------
#define SCHUNK 49
__global__ void mean1_kernel(const float* __restrict__ x, float* __restrict__ part) {
    int d4 = blockIdx.x * 256 + threadIdx.x;
    int b = blockIdx.y;
    int sc = blockIdx.z;
    const float4* xp = (const float4*)(x + (size_t)b * S_ * D_) + (size_t)(sc * SCHUNK) * (D_ / 4) + d4;
    float4 s = make_float4(0.f, 0.f, 0.f, 0.f);
    #pragma unroll 7
    for (int i = 0; i < SCHUNK; ++i) {
        float4 v = __ldcs(xp + (size_t)i * (D_ / 4));
        s.x += v.x; s.y += v.y; s.z += v.z; s.w += v.w;
    }
    ((float4*)(part + ((size_t)sc * B_ + b) * D_))[d4] = s;
}
__global__ void mean2_kernel(const float* __restrict__ part, float* __restrict__ xm) {
    int i4 = blockIdx.x * 256 + threadIdx.x;
    const float4* p = (const float4*)part + i4;
    const int str = B_ * D_ / 4;
    float4 a = p[0], b = p[str], c = p[2 * str], d = p[3 * str];
    const float inv = 1.0f / S_;
    ((float4*)xm)[i4] = make_float4((a.x + b.x + c.x + d.x) * inv,
                                    (a.y + b.y + c.y + d.y) * inv,
                                    (a.z + b.z + c.z + d.z) * inv,
                                    (a.w + b.w + c.w + d.w) * inv);
}

// ---------------- unified TC TN GEMM, fp32 in/out, in-reg bf16 ----------------
// C = (Σ_{s<SPLITA} A_s + Abias) @ B^T.  NSPLIT 3 = hi/lo split; 1 = bf16.
// Output: C += zb*sCz + sk*sCs (partials when SPLITK>1).
// SWAP: m-tile on blockIdx.x (consecutive blocks share the B tile -> L2 reuse).
template<int NSPLIT, int SPLITK, int BM, int SPLITA, bool SWAP>
__global__ __launch_bounds__(256) void bgemm3_kernel(
    const float* __restrict__ A, int lda, long long sAz, long long sAs,
    const float* __restrict__ Abias, int sAbz,
    const float* __restrict__ Bm, int ldb, long long sBz,
    float* __restrict__ C, int ldc, long long sCz, long long sCs,
    int M, int N, int K)
{
    extern __shared__ __nv_bfloat16 sm[];
    constexpr int APLANE = BM * 32;
    constexpr int LO_OFF = APLANE + 4096;
    constexpr int STAGE  = LO_OFF * ((NSPLIT == 3) ? 2 : 1);
    constexpr int N8     = (BM == 128) ? 8 : 4;
    const int tid = threadIdx.x, lane = tid & 31, warp = tid >> 5;
    const int warpM = (BM == 128) ? (warp >> 1) * 32 : (warp >> 2) * 32;
    const int warpN = (BM == 128) ? (warp & 1) * 64 : (warp & 3) * 32;
    const int m0 = (SWAP ? blockIdx.x : blockIdx.y) * BM;
    const int n0 = (SWAP ? blockIdx.y : blockIdx.x) * 128;
    const int zb = blockIdx.z / SPLITK, sk = blockIdx.z % SPLITK;
    const int Kc = K / SPLITK, k0base = sk * Kc;

    A  += (size_t)zb * sAz;
    Bm += (size_t)zb * sBz;
    C  += (size_t)zb * sCz + (size_t)sk * sCs;

    const int cc = tid & 7, rr = tid >> 3;
    float4 ra[BM / 32], rb[4];
    unsigned sbase = (unsigned)__cvta_generic_to_shared(sm);

    float acc[2][N8][4];
    #pragma unroll
    for (int a = 0; a < 2; ++a)
        #pragma unroll
        for (int b = 0; b < N8; ++b)
            #pragma unroll
            for (int c = 0; c < 4; ++c) acc[a][b][c] = 0.f;

    auto ldg = [&](int kt) {
        int kcol = k0base + kt * 32 + cc * 4;
        #pragma unroll
        for (int j = 0; j < BM / 32; ++j) {
            int rA = m0 + j * 32 + rr;
            float4 v = make_float4(0.f, 0.f, 0.f, 0.f);
            if (rA < M) {
                v = *(const float4*)(A + (size_t)rA * lda + kcol);
                #pragma unroll
                for (int s = 1; s < SPLITA; ++s) {
                    float4 w = *(const float4*)(A + (size_t)s * sAs + (size_t)rA * lda + kcol);
                    v.x += w.x; v.y += w.y; v.z += w.z; v.w += w.w;
                }
                if (Abias) {
                    float4 bb = *(const float4*)(Abias + (size_t)zb * sAbz + kcol);
                    v.x += bb.x; v.y += bb.y; v.z += bb.z; v.w += bb.w;
                }
            }
            ra[j] = v;
        }
        #pragma unroll
        for (int j = 0; j < 4; ++j) {
            int rB = n0 + j * 32 + rr;
            rb[j] = (rB < N) ? *(const float4*)(Bm + (size_t)rB * ldb + kcol)
                             : make_float4(0.f, 0.f, 0.f, 0.f);
        }
    };
    auto sts = [&](int s) {
        __nv_bfloat16* base = sm + s * STAGE;
        unsigned h0, h1, l0, l1;
        #pragma unroll
        for (int j = 0; j < BM / 32; ++j) {
            int row = j * 32 + rr;
            int off = row * 32 + ((((cc >> 1) ^ ((row >> 1) & 3)) << 3)) + ((cc & 1) << 2);
            split2(ra[j].x, ra[j].y, h0, l0);
            split2(ra[j].z, ra[j].w, h1, l1);
            *(uint2*)(base + off) = make_uint2(h0, h1);
            if (NSPLIT == 3) *(uint2*)(base + LO_OFF + off) = make_uint2(l0, l1);
        }
        #pragma unroll
        for (int j = 0; j < 4; ++j) {
            int row = j * 32 + rr;
            int off = APLANE + row * 32 + ((((cc >> 1) ^ ((row >> 1) & 3)) << 3)) + ((cc & 1) << 2);
            split2(rb[j].x, rb[j].y, h0, l0);
            split2(rb[j].z, rb[j].w, h1, l1);
            *(uint2*)(base + off) = make_uint2(h0, h1);
            if (NSPLIT == 3) *(uint2*)(base + LO_OFF + off) = make_uint2(l0, l1);
        }
    };
    auto compute = [&](int s) {
        unsigned aB = sbase + (unsigned)(s * STAGE) * 2u;
        unsigned bB = aB + (unsigned)APLANE * 2u;
        #pragma unroll
        for (int kk = 0; kk < 32; kk += 16) {
            unsigned ah[2][4], al[2][4];
            #pragma unroll
            for (int mi = 0; mi < 2; ++mi) {
                int row = warpM + mi * 16 + (lane & 15);
                int ch = (kk >> 3) + (lane >> 4);
                unsigned addr = aB +
                    (unsigned)(row * 32 + ((ch ^ ((row >> 1) & 3)) << 3)) * 2u;
                LDSM4(ah[mi], addr);
                if (NSPLIT == 3) LDSM4(al[mi], addr + (unsigned)LO_OFF * 2u);
            }
            unsigned bh[N8 / 2][4], bl[N8 / 2][4];
            #pragma unroll
            for (int ni = 0; ni < N8 / 2; ++ni) {
                int g = lane >> 3;
                int row = warpN + ni * 16 + ((g >> 1) << 3) + (lane & 7);
                int ch = (kk >> 3) + (g & 1);
                unsigned addr = bB +
                    (unsigned)(row * 32 + ((ch ^ ((row >> 1) & 3)) << 3)) * 2u;
                LDSM4(bh[ni], addr);
                if (NSPLIT == 3) LDSM4(bl[ni], addr + (unsigned)LO_OFF * 2u);
            }
            #pragma unroll
            for (int mi = 0; mi < 2; ++mi)
                #pragma unroll
                for (int n8 = 0; n8 < N8; ++n8) {
                    unsigned* hb = &bh[n8 >> 1][(n8 & 1) * 2];
                    MMA16816(acc[mi][n8], ah[mi], hb[0], hb[1]);
                    if (NSPLIT == 3) {
                        unsigned* lb = &bl[n8 >> 1][(n8 & 1) * 2];
                        MMA16816(acc[mi][n8], ah[mi], lb[0], lb[1]);
                        MMA16816(acc[mi][n8], al[mi], hb[0], hb[1]);
                    }
                }
        }
    };

    const int KT = Kc / 32;
    ldg(0);
    sts(0);
    __syncthreads();
    for (int t = 0; t < KT; ++t) {
        if (t + 1 < KT) ldg(t + 1);
        compute(t & 1);
        __syncthreads();
        if (t + 1 < KT) { sts((t + 1) & 1); __syncthreads(); }
    }

    #pragma unroll
    for (int mi = 0; mi < 2; ++mi) {
        int row = m0 + warpM + mi * 16 + (lane >> 2);
        #pragma unroll
        for (int n8 = 0; n8 < N8; ++n8) {
            int col = n0 + warpN + n8 * 8 + (lane & 3) * 2;
            if (row < M)
                *(float2*)(C + (size_t)row * ldc + col) =
                    make_float2(acc[mi][n8][0], acc[mi][n8][1]);
            if (row + 8 < M)
                *(float2*)(C + (size_t)(row + 8) * ldc + col) =
                    make_float2(acc[mi][n8][2], acc[mi][n8][3]);
        }
    }
}

// ---------------- split-K reduce (+bias, +gelu) ----------------
template<int EPI>
__global__ void reduce_kernel(const float* __restrict__ part, float* __restrict__ C,
                              int ldc, const float* __restrict__ bias,
                              int MN, int N, int SPLIT)
{
    int i = blockIdx.x * 256 + threadIdx.x;
    if (i >= MN) return;
    const float* p = part + i;
    float s = 0.f;
    for (int k = 0; k < SPLIT; ++k) s += p[(size_t)k * MN];
    int n = i % N;
    if (bias) s += bias[n];
    if (EPI == 1) s = gelu_exact(s);
    C[(size_t)(i / N) * ldc + n] = s;
}

// ---------------- top-64 coarse -> exact fp32 rescore -> top-32 + z ----------
__global__ __launch_bounds__(256) void topk_kernel(
    const float* __restrict__ scores, const float* __restrict__ u,
    const float* __restrict__ mem, float* __restrict__ z)
{
    extern __shared__ float dyn[];
    float* sv = dyn;
    float* us = dyn + M_;
    __shared__ float warpv[8];
    __shared__ int   warpi[8];
    __shared__ int   s_wini;
    __shared__ int   cand[64];
    __shared__ float scE[64];
    __shared__ float pw[KSEL];
    __shared__ int   pidx[KSEL];

    const int row = blockIdx.x, tid = threadIdx.x;
    const int lane = tid & 31, warp = tid >> 5;
    const float* sr = scores + (size_t)row * M_;
    const float* ur = u + (size_t)row * D_;

    float bv = -INFINITY; int bi = 0;
    #pragma unroll 4
    for (int j = 0; j < M_ / 256; ++j) {
        int i = tid + j * 256;
        float v = __ldcs(&sr[i]);
        sv[i] = v;
        if (v > bv) { bv = v; bi = i; }
    }
    for (int j = tid; j < D_; j += 256) us[j] = ur[j];
    __syncthreads();

    for (int sel = 0; sel < 64; ++sel) {
        float v = bv; int ix = bi;
        #pragma unroll
        for (int o = 16; o > 0; o >>= 1) {
            float v2 = __shfl_down_sync(0xffffffffu, v, o);
            int   i2 = __shfl_down_sync(0xffffffffu, ix, o);
            if (v2 > v || (v2 == v && i2 < ix)) { v = v2; ix = i2; }
        }
        if (lane == 0) { warpv[warp] = v; warpi[warp] = ix; }
        __syncthreads();
        if (warp == 0) {
            float v3 = (lane < 8) ? warpv[lane] : -INFINITY;
            int   i3 = (lane < 8) ? warpi[lane] : 0x7fffffff;
            #pragma unroll
            for (int o = 4; o > 0; o >>= 1) {
                float v2 = __shfl_down_sync(0xffffffffu, v3, o);
                int   i2 = __shfl_down_sync(0xffffffffu, i3, o);
                if (v2 > v3 || (v2 == v3 && i2 < i3)) { v3 = v2; i3 = i2; }
            }
            if (lane == 0) { s_wini = i3; cand[sel] = i3; }
        }
        __syncthreads();
        int w = s_wini;
        if ((w & 255) == tid) {
            sv[w] = -INFINITY;
            bv = -INFINITY; bi = 0;
            #pragma unroll 4
            for (int j = 0; j < M_ / 256; ++j) {
                int i = tid + j * 256;
                float vv = sv[i];
                if (vv > bv) { bv = vv; bi = i; }
            }
        }
        __syncthreads();
    }

    for (int r8 = 0; r8 < 8; ++r8) {
        int c = r8 * 8 + warp;
        const float* mr = mem + (size_t)cand[c] * D_;
        float s = 0.f;
        #pragma unroll 8
        for (int j = lane; j < D_; j += 32) s += us[j] * mr[j];
        #pragma unroll
        for (int o = 16; o > 0; o >>= 1) s += __shfl_down_sync(0xffffffffu, s, o);
        if (lane == 0) scE[c] = s;
    }
    __syncthreads();

    if (warp == 0) {
        float v0 = scE[lane], v1 = scE[32 + lane];
        int   i0 = cand[lane], i1 = cand[32 + lane];
        for (int s = 0; s < KSEL; ++s) {
            float v; int ix, slot;
            if (v0 > v1 || (v0 == v1 && i0 < i1)) { v = v0; ix = i0; slot = lane; }
            else                                  { v = v1; ix = i1; slot = 32 + lane; }
            #pragma unroll
            for (int o = 16; o > 0; o >>= 1) {
                float v2 = __shfl_down_sync(0xffffffffu, v, o);
                int   x2 = __shfl_down_sync(0xffffffffu, ix, o);
                int   s2 = __shfl_down_sync(0xffffffffu, slot, o);
                if (v2 > v || (v2 == v && x2 < ix)) { v = v2; ix = x2; slot = s2; }
            }
            v    = __shfl_sync(0xffffffffu, v, 0);
            ix   = __shfl_sync(0xffffffffu, ix, 0);
            slot = __shfl_sync(0xffffffffu, slot, 0);
            if (slot == lane)      v0 = -INFINITY;
            if (slot == 32 + lane) v1 = -INFINITY;
            if (lane == 0) { pw[s] = v; pidx[s] = ix; }
        }
        if (lane == 0) {
            float mx = pw[0], ssum = 0.f;
            for (int k = 0; k < KSEL; ++k) {
                float e = expf((pw[k] - mx) * 0.0625f);
                pw[k] = e; ssum += e;
            }
            float inv = 1.f / ssum;
            for (int k = 0; k < KSEL; ++k) pw[k] *= inv;
        }
    }
    __syncthreads();

    for (int d = tid; d < D_; d += 256) {
        float acc = 0.f;
        #pragma unroll
        for (int k = 0; k < KSEL; ++k) acc += pw[k] * mem[(size_t)pidx[k] * D_ + d];
        z[(size_t)row * D_ + d] = acc;
    }
}

// ---------------- head: exact fp32 warp-per-output dot ------------------------
__global__ void head_kernel(const float* __restrict__ fus, const float* __restrict__ hw,
                            const float* __restrict__ hb, float* __restrict__ out)
{
    int gw = (blockIdx.x * blockDim.x + threadIdx.x) >> 5;
    int lane = threadIdx.x & 31;
    if (gw >= B_ * C_) return;
    int b = gw / C_, c = gw % C_;
    const float4* fr = (const float4*)(fus + (size_t)b * D_);
    const float4* wr = (const float4*)(hw + (size_t)c * D_);
    float s = 0.f;
    #pragma unroll 4
    for (int j = lane; j < D_ / 4; j += 32) {
        float4 f = fr[j], w = wr[j];
        s += f.x * w.x + f.y * w.y + f.z * w.z + f.w * w.w;
    }
    #pragma unroll
    for (int o = 16; o > 0; o >>= 1) s += __shfl_down_sync(0xffffffffu, s, o);
    if (lane == 0) out[b * C_ + c] = s + hb[c];
}

// ---------------- launch --------------------------------------------------------
extern "C" void kernel_launch(void* const* d_in, const int* in_sizes, int n_in,
                              void* d_out, int out_size)
{
    const float* x      = (const float*)d_in[0];
    const float* mem    = (const float*)d_in[2];
    const float* ff_w   = (const float*)d_in[3];
    const float* ff_b   = (const float*)d_in[4];
    const float* mp_w   = (const float*)d_in[5];
    const float* mp_b   = (const float*)d_in[6];
    const float* wq     = (const float*)d_in[7];
    const float* bq     = (const float*)d_in[8];
    const float* wk     = (const float*)d_in[9];
    const float* wv     = (const float*)d_in[11];
    const float* bv     = (const float*)d_in[12];
    const float* wo     = (const float*)d_in[13];
    const float* bo     = (const float*)d_in[14];
    const float* fuse_w = (const float*)d_in[15];
    const float* fuse_b = (const float*)d_in[16];
    const float* head_w = (const float*)d_in[17];
    const float* head_b = (const float*)d_in[18];
    float* out = (float*)d_out;

    float *xm, *t, *u, *sc, *z, *fin, *fus, *part, *wkT, *mpwT;
    cudaGetSymbolAddress((void**)&xm,   g_xm);
    cudaGetSymbolAddress((void**)&t,    g_t);
    cudaGetSymbolAddress((void**)&u,    g_u);
    cudaGetSymbolAddress((void**)&sc,   g_sc);
    cudaGetSymbolAddress((void**)&z,    g_z);
    cudaGetSymbolAddress((void**)&fin,  g_fin);
    cudaGetSymbolAddress((void**)&fus,  g_fus);
    cudaGetSymbolAddress((void**)&part, g_part);
    cudaGetSymbolAddress((void**)&wkT,  g_wkT);
    cudaGetSymbolAddress((void**)&mpwT, g_mpwT);

    cudaFuncSetAttribute((const void*)bgemm3_kernel<3,8,64,1,false>,  cudaFuncAttributeMaxDynamicSharedMemorySize, 49152);
    cudaFuncSetAttribute((const void*)bgemm3_kernel<3,8,64,8,false>,  cudaFuncAttributeMaxDynamicSharedMemorySize, 49152);
    cudaFuncSetAttribute((const void*)bgemm3_kernel<3,1,64,8,false>,  cudaFuncAttributeMaxDynamicSharedMemorySize, 49152);
    cudaFuncSetAttribute((const void*)bgemm3_kernel<3,2,128,1,false>, cudaFuncAttributeMaxDynamicSharedMemorySize, 65536);
    cudaFuncSetAttribute((const void*)bgemm3_kernel<1,1,128,1,true>,  cudaFuncAttributeMaxDynamicSharedMemorySize, 32768);
    cudaFuncSetAttribute((const void*)bgemm3_kernel<1,2,128,1,false>, cudaFuncAttributeMaxDynamicSharedMemorySize, 32768);
    cudaFuncSetAttribute((const void*)bgemm3_kernel<1,4,64,2,false>,  cudaFuncAttributeMaxDynamicSharedMemorySize, 24576);
    cudaFuncSetAttribute((const void*)bgemm3_kernel<1,8,64,4,false>,  cudaFuncAttributeMaxDynamicSharedMemorySize, 24576);
    cudaFuncSetAttribute((const void*)topk_kernel, cudaFuncAttributeMaxDynamicSharedMemorySize, (M_ + D_) * 4);

    const long long BD  = (long long)B_ * D_;
    const long long BHD = (long long)B_ * H_ * D_;

    // prep
    transpose_kernel<<<dim3(64, 64), dim3(32, 8)>>>(wk, wkT);
    transpose_kernel<<<dim3(64, 64), dim3(32, 8)>>>(mp_w, mpwT);

    // 1) xm = mean_s(x)
    mean1_kernel<<<dim3(2, B_, 4), 256>>>(x, part);
    mean2_kernel<<<B_ * D_ / 1024, 256>>>(part, xm);

    // 2) xf partials: xm @ ff_w^T -> part0 (8 planes)
    bgemm3_kernel<3,8,64,1,false><<<dim3(16, 1, 8), 256, 49152>>>(
        xm, D_, 0, 0, nullptr, 0, ff_w, D_, 0,
        part + PART0, D_, 0, BD, B_, D_, D_);

    // 3) q partials: (Σ xf_part + ff_b) @ wq^T -> part1 (8 planes)
    bgemm3_kernel<3,8,64,8,false><<<dim3(16, 1, 8), 256, 49152>>>(
        part + PART0, D_, 0, BD, ff_b, 0, wq, D_, 0,
        part + PART1, D_, 0, BD, B_, D_, D_);

    // 4) fin[:, :D] = xf (reduce part0 + ff_b)
    reduce_kernel<0><<<dim3(512, 1), 256>>>(
        part + PART0, fin, 2 * D_, ff_b, B_ * D_, D_, 8);

    // 5) t = (Σ q_part + bq)_h @ wk_h (TN via wkT; head offset = 256 COLUMNS)
    bgemm3_kernel<3,1,64,8,false><<<dim3(16, 1, H_), 256, 49152>>>(
        part + PART1, D_, DK_, BD, bq, DK_, wkT, D_, (long long)DK_,
        t, H_ * D_, D_, 0, B_, D_, DK_);

    // 6) u partials: t @ mp_w (TN via mpwT), split-K 2 -> part0
    bgemm3_kernel<3,2,128,1,false><<<dim3(16, 4, 2), 256, 65536>>>(
        t, D_, 0, 0, nullptr, 0, mpwT, D_, 0,
        part + PART0, D_, 0, BHD, B_ * H_, D_, D_);
    reduce_kernel<0><<<dim3(4096, 1), 256>>>(
        part + PART0, u, D_, nullptr, B_ * H_ * D_, D_, 2);

    // 7) scores = u @ mem^T (fp32 in, bf16 TC; SWAP grid for mem L2 reuse)
    bgemm3_kernel<1,1,128,1,true><<<dim3(4, 128, 1), 256, 32768>>>(
        u, D_, 0, 0, nullptr, 0, mem, D_, 0,
        sc, M_, 0, 0, B_ * H_, M_, D_);

    // 8) topk -> z
    topk_kernel<<<B_ * H_, 256, (M_ + D_) * 4>>>(sc, u, mem, z);

    // 9) y partials: z @ mp_w^T, split-K 2 -> part0
    bgemm3_kernel<1,2,128,1,false><<<dim3(16, 4, 2), 256, 32768>>>(
        z, D_, 0, 0, nullptr, 0, mp_w, D_, 0,
        part + PART0, D_, 0, BHD, B_ * H_, D_, D_);

    // 10) attn partials: (Σ y_part + mp_b)_h @ wv_h^T, split-K 4 -> part2
    bgemm3_kernel<1,4,64,2,false><<<dim3(2, 1, H_ * 4), 256, 24576>>>(
        part + PART0, H_ * D_, D_, BHD, mp_b, 0, wv, D_, (long long)DK_ * D_,
        part + PART2, D_, DK_, BD, B_, DK_, D_);

    // 11) resp partials: (Σ attn_part + bv) @ wo^T, split-K 8 -> part0
    bgemm3_kernel<1,8,64,4,false><<<dim3(16, 1, 8), 256, 24576>>>(
        part + PART2, D_, 0, BD, bv, 0, wo, D_, 0,
        part + PART0, D_, 0, BD, B_, D_, D_);

    // 12) fin[:, D:] = resp (reduce part0 + bo)
    reduce_kernel<0><<<dim3(512, 1), 256>>>(
        part + PART0, fin + D_, 2 * D_, bo, B_ * D_, D_, 8);

    // 13) fus = gelu((fin @ fuse_w^T) + fuse_b), split-K 8 -> part1
    bgemm3_kernel<3,8,64,1,false><<<dim3(16, 1, 8), 256, 49152>>>(
        fin, 2 * D_, 0, 0, nullptr, 0, fuse_w, 2 * D_, 0,
        part + PART1, D_, 0, BD, B_, D_, 2 * D_);
    reduce_kernel<1><<<dim3(512, 1), 256>>>(
        part + PART1, fus, D_, fuse_b, B_ * D_, D_, 8);

    // 14) logits (exact fp32)
    head_kernel<<<(B_ * C_ * 32 + 255) / 256, 256>>>(fus, head_w, head_b, out);
}

// round 8
// speedup vs baseline: 1.0571x; 1.0571x over previous
#include <cuda_runtime.h>
#include <cuda_bf16.h>
#include <math.h>

#define B_  64
#define S_  196
#define D_  2048
#define H_  8
#define DK_ 256
#define M_  16384
#define KSEL 32
#define C_  29

__device__ float g_xm [B_ * D_];
__device__ float g_t  [B_ * H_ * D_];
__device__ float g_u  [B_ * H_ * D_];
__device__ float g_sc [B_ * H_ * M_];
__device__ float g_z  [B_ * H_ * D_];
__device__ float g_fin[B_ * 2 * D_];
__device__ float g_fus[B_ * D_];
__device__ float g_part[4 * 512 * 2048];   // 16 MB scratch, region-multiplexed
__device__ float g_wkT [D_ * D_];
__device__ float g_mpwT[D_ * D_];
__device__ __nv_bfloat16 g_u_bf [B_ * H_ * D_];
__device__ __nv_bfloat16 g_mem_bf[M_ * D_];

#define PART0 0
#define PART1 (1024 * 1024)      // +4 MB (in floats)
#define PART2 (2 * 1024 * 1024)  // +8 MB

__device__ __forceinline__ float gelu_exact(float v) {
    return 0.5f * v * (1.0f + erff(v * 0.70710678118654752f));
}
__device__ __forceinline__ void split2(float a, float b, unsigned& hi, unsigned& lo) {
    __nv_bfloat162 h = __floats2bfloat162_rn(a, b);
    __nv_bfloat162 l = __floats2bfloat162_rn(a - __bfloat162float(h.x),
                                             b - __bfloat162float(h.y));
    hi = *(unsigned*)&h; lo = *(unsigned*)&l;
}

#define LDSM4(R, ADDR) asm volatile( \
    "ldmatrix.sync.aligned.m8n8.x4.shared.b16 {%0,%1,%2,%3}, [%4];" \
    : "=r"((R)[0]), "=r"((R)[1]), "=r"((R)[2]), "=r"((R)[3]) : "r"(ADDR))
#define MMA16816(D, A, B0, B1) asm volatile( \
    "mma.sync.aligned.m16n8k16.row.col.f32.bf16.bf16.f32 " \
    "{%0,%1,%2,%3},{%4,%5,%6,%7},{%8,%9},{%0,%1,%2,%3};" \
    : "+f"((D)[0]), "+f"((D)[1]), "+f"((D)[2]), "+f"((D)[3]) \
    : "r"((A)[0]), "r"((A)[1]), "r"((A)[2]), "r"((A)[3]), "r"(B0), "r"(B1))

// ---------------- transpose fp32 DxD ----------------
__global__ void transpose_kernel(const float* __restrict__ in, float* __restrict__ out) {
    __shared__ float tile[32][33];
    int x = blockIdx.x * 32 + threadIdx.x;
    #pragma unroll
    for (int j = threadIdx.y; j < 32; j += 8)
        tile[j][threadIdx.x] = __ldcs(&in[(size_t)(blockIdx.y * 32 + j) * D_ + x]);
    __syncthreads();
    int xo = blockIdx.y * 32 + threadIdx.x;
    #pragma unroll
    for (int j = threadIdx.y; j < 32; j += 8)
        out[(size_t)(blockIdx.x * 32 + j) * D_ + xo] = tile[threadIdx.x][j];
}

// ---------------- fp32 -> bf16, streaming, 16 elems/thread ----------------
__global__ void f2b_kernel(const float* __restrict__ a, __nv_bfloat16* __restrict__ o, int n) {
    int stride = gridDim.x * blockDim.x * 16;
    for (int i = (blockIdx.x * blockDim.x + threadIdx.x) * 16; i < n; i += stride) {
        float4 v0 = __ldcs((const float4*)(a + i));
        float4 v1 = __ldcs((const float4*)(a + i + 4));
        float4 v2 = __ldcs((const float4*)(a + i + 8));
        float4 v3 = __ldcs((const float4*)(a + i + 12));
        __nv_bfloat162 r[8];
        r[0] = __floats2bfloat162_rn(v0.x, v0.y);
        r[1] = __floats2bfloat162_rn(v0.z, v0.w);
        r[2] = __floats2bfloat162_rn(v1.x, v1.y);
        r[3] = __floats2bfloat162_rn(v1.z, v1.w);
        r[4] = __floats2bfloat162_rn(v2.x, v2.y);
        r[5] = __floats2bfloat162_rn(v2.z, v2.w);
        r[6] = __floats2bfloat162_rn(v3.x, v3.y);
        r[7] = __floats2bfloat162_rn(v3.z, v3.w);
        __stcs((uint4*)(o + i),     *(uint4*)&r[0]);
        __stcs((uint4*)(o + i + 8), *(uint4*)&r[4]);
    }
}

// ---------------- mean over S: two phase ----------------
#define SCHUNK 49
__global__ void mean1_kernel(const float* __restrict__ x, float* __restrict__ part) {
    int d4 = blockIdx.x * 256 + threadIdx.x;
    int b = blockIdx.y;
    int sc = blockIdx.z;
    const float4* xp = (const float4*)(x + (size_t)b * S_ * D_) + (size_t)(sc * SCHUNK) * (D_ / 4) + d4;
    float4 s = make_float4(0.f, 0.f, 0.f, 0.f);
    #pragma unroll 7
    for (int i = 0; i < SCHUNK; ++i) {
        float4 v = __ldcs(xp + (size_t)i * (D_ / 4));
        s.x += v.x; s.y += v.y; s.z += v.z; s.w += v.w;
    }
    ((float4*)(part + ((size_t)sc * B_ + b) * D_))[d4] = s;
}
__global__ void mean2_kernel(const float* __restrict__ part, float* __restrict__ xm) {
    int i4 = blockIdx.x * 256 + threadIdx.x;
    const float4* p = (const float4*)part + i4;
    const int str = B_ * D_ / 4;
    float4 a = p[0], b = p[str], c = p[2 * str], d = p[3 * str];
    const float inv = 1.0f / S_;
    ((float4*)xm)[i4] = make_float4((a.x + b.x + c.x + d.x) * inv,
                                    (a.y + b.y + c.y + d.y) * inv,
                                    (a.z + b.z + c.z + d.z) * inv,
                                    (a.w + b.w + c.w + d.w) * inv);
}

// ---------------- unified TC TN GEMM, fp32 in/out, in-reg bf16 ----------------
// C = (Σ_{s<SPLITA} A_s + Abias) @ B^T.  NSPLIT 3 = hi/lo split; 1 = bf16.
template<int NSPLIT, int SPLITK, int BM, int SPLITA>
__global__ __launch_bounds__(256) void bgemm3_kernel(
    const float* __restrict__ A, int lda, long long sAz, long long sAs,
    const float* __restrict__ Abias, int sAbz,
    const float* __restrict__ Bm, int ldb, long long sBz,
    float* __restrict__ C, int ldc, long long sCz, long long sCs,
    int M, int N, int K)
{
    extern __shared__ __nv_bfloat16 sm[];
    constexpr int APLANE = BM * 32;
    constexpr int LO_OFF = APLANE + 4096;
    constexpr int STAGE  = LO_OFF * ((NSPLIT == 3) ? 2 : 1);
    constexpr int N8     = (BM == 128) ? 8 : 4;
    const int tid = threadIdx.x, lane = tid & 31, warp = tid >> 5;
    const int warpM = (BM == 128) ? (warp >> 1) * 32 : (warp >> 2) * 32;
    const int warpN = (BM == 128) ? (warp & 1) * 64 : (warp & 3) * 32;
    const int m0 = blockIdx.y * BM;
    const int n0 = blockIdx.x * 128;
    const int zb = blockIdx.z / SPLITK, sk = blockIdx.z % SPLITK;
    const int Kc = K / SPLITK, k0base = sk * Kc;

    A  += (size_t)zb * sAz;
    Bm += (size_t)zb * sBz;
    C  += (size_t)zb * sCz + (size_t)sk * sCs;

    const int cc = tid & 7, rr = tid >> 3;
    float4 ra[BM / 32], rb[4];
    unsigned sbase = (unsigned)__cvta_generic_to_shared(sm);

    float acc[2][N8][4];
    #pragma unroll
    for (int a = 0; a < 2; ++a)
        #pragma unroll
        for (int b = 0; b < N8; ++b)
            #pragma unroll
            for (int c = 0; c < 4; ++c) acc[a][b][c] = 0.f;

    auto ldg = [&](int kt) {
        int kcol = k0base + kt * 32 + cc * 4;
        #pragma unroll
        for (int j = 0; j < BM / 32; ++j) {
            int rA = m0 + j * 32 + rr;
            float4 v = make_float4(0.f, 0.f, 0.f, 0.f);
            if (rA < M) {
                v = *(const float4*)(A + (size_t)rA * lda + kcol);
                #pragma unroll
                for (int s = 1; s < SPLITA; ++s) {
                    float4 w = *(const float4*)(A + (size_t)s * sAs + (size_t)rA * lda + kcol);
                    v.x += w.x; v.y += w.y; v.z += w.z; v.w += w.w;
                }
                if (Abias) {
                    float4 bb = *(const float4*)(Abias + (size_t)zb * sAbz + kcol);
                    v.x += bb.x; v.y += bb.y; v.z += bb.z; v.w += bb.w;
                }
            }
            ra[j] = v;
        }
        #pragma unroll
        for (int j = 0; j < 4; ++j) {
            int rB = n0 + j * 32 + rr;
            rb[j] = (rB < N) ? *(const float4*)(Bm + (size_t)rB * ldb + kcol)
                             : make_float4(0.f, 0.f, 0.f, 0.f);
        }
    };
    auto sts = [&](int s) {
        __nv_bfloat16* base = sm + s * STAGE;
        unsigned h0, h1, l0, l1;
        #pragma unroll
        for (int j = 0; j < BM / 32; ++j) {
            int row = j * 32 + rr;
            int off = row * 32 + ((((cc >> 1) ^ ((row >> 1) & 3)) << 3)) + ((cc & 1) << 2);
            split2(ra[j].x, ra[j].y, h0, l0);
            split2(ra[j].z, ra[j].w, h1, l1);
            *(uint2*)(base + off) = make_uint2(h0, h1);
            if (NSPLIT == 3) *(uint2*)(base + LO_OFF + off) = make_uint2(l0, l1);
        }
        #pragma unroll
        for (int j = 0; j < 4; ++j) {
            int row = j * 32 + rr;
            int off = APLANE + row * 32 + ((((cc >> 1) ^ ((row >> 1) & 3)) << 3)) + ((cc & 1) << 2);
            split2(rb[j].x, rb[j].y, h0, l0);
            split2(rb[j].z, rb[j].w, h1, l1);
            *(uint2*)(base + off) = make_uint2(h0, h1);
            if (NSPLIT == 3) *(uint2*)(base + LO_OFF + off) = make_uint2(l0, l1);
        }
    };
    auto compute = [&](int s) {
        unsigned aB = sbase + (unsigned)(s * STAGE) * 2u;
        unsigned bB = aB + (unsigned)APLANE * 2u;
        #pragma unroll
        for (int kk = 0; kk < 32; kk += 16) {
            unsigned ah[2][4], al[2][4];
            #pragma unroll
            for (int mi = 0; mi < 2; ++mi) {
                int row = warpM + mi * 16 + (lane & 15);
                int ch = (kk >> 3) + (lane >> 4);
                unsigned addr = aB +
                    (unsigned)(row * 32 + ((ch ^ ((row >> 1) & 3)) << 3)) * 2u;
                LDSM4(ah[mi], addr);
                if (NSPLIT == 3) LDSM4(al[mi], addr + (unsigned)LO_OFF * 2u);
            }
            unsigned bh[N8 / 2][4], bl[N8 / 2][4];
            #pragma unroll
            for (int ni = 0; ni < N8 / 2; ++ni) {
                int g = lane >> 3;
                int row = warpN + ni * 16 + ((g >> 1) << 3) + (lane & 7);
                int ch = (kk >> 3) + (g & 1);
                unsigned addr = bB +
                    (unsigned)(row * 32 + ((ch ^ ((row >> 1) & 3)) << 3)) * 2u;
                LDSM4(bh[ni], addr);
                if (NSPLIT == 3) LDSM4(bl[ni], addr + (unsigned)LO_OFF * 2u);
            }
            #pragma unroll
            for (int mi = 0; mi < 2; ++mi)
                #pragma unroll
                for (int n8 = 0; n8 < N8; ++n8) {
                    unsigned* hb = &bh[n8 >> 1][(n8 & 1) * 2];
                    MMA16816(acc[mi][n8], ah[mi], hb[0], hb[1]);
                    if (NSPLIT == 3) {
                        unsigned* lb = &bl[n8 >> 1][(n8 & 1) * 2];
                        MMA16816(acc[mi][n8], ah[mi], lb[0], lb[1]);
                        MMA16816(acc[mi][n8], al[mi], hb[0], hb[1]);
                    }
                }
        }
    };

    const int KT = Kc / 32;
    ldg(0);
    sts(0);
    __syncthreads();
    for (int t = 0; t < KT; ++t) {
        if (t + 1 < KT) ldg(t + 1);
        compute(t & 1);
        __syncthreads();
        if (t + 1 < KT) { sts((t + 1) & 1); __syncthreads(); }
    }

    #pragma unroll
    for (int mi = 0; mi < 2; ++mi) {
        int row = m0 + warpM + mi * 16 + (lane >> 2);
        #pragma unroll
        for (int n8 = 0; n8 < N8; ++n8) {
            int col = n0 + warpN + n8 * 8 + (lane & 3) * 2;
            if (row < M)
                *(float2*)(C + (size_t)row * ldc + col) =
                    make_float2(acc[mi][n8][0], acc[mi][n8][1]);
            if (row + 8 < M)
                *(float2*)(C + (size_t)(row + 8) * ldc + col) =
                    make_float2(acc[mi][n8][2], acc[mi][n8][3]);
        }
    }
}

// ---------------- split-K reduce (+bias, +gelu, +bf16 mirror) ----------------
template<int EPI, bool WBF>
__global__ void reduce_kernel(const float* __restrict__ part, float* __restrict__ C,
                              int ldc, const float* __restrict__ bias,
                              __nv_bfloat16* __restrict__ Cbf,
                              int MN, int N, int SPLIT)
{
    int i = blockIdx.x * 256 + threadIdx.x;
    if (i >= MN) return;
    const float* p = part + i;
    float s = 0.f;
    for (int k = 0; k < SPLIT; ++k) s += p[(size_t)k * MN];
    int n = i % N;
    if (bias) s += bias[n];
    if (EPI == 1) s = gelu_exact(s);
    C[(size_t)(i / N) * ldc + n] = s;
    if (WBF) Cbf[i] = __float2bfloat16(s);
}

// ---------------- scores: bf16 TC TN GEMM, 3-stage cp.async -------------------
// Grid (BH/128, M/128) with m-tiles on blockIdx.x so co-resident blocks share
// each mem B-tile via L2 (mem_bf streamed ~once).
__device__ __forceinline__ unsigned bswz(int row, int chunk) {
    return (unsigned)(row * 64 + ((chunk ^ (row & 7)) * 8));
}
__global__ __launch_bounds__(256) void bgemm_kernel(
    const __nv_bfloat16* __restrict__ A, int lda,
    const __nv_bfloat16* __restrict__ B, int ldb,
    float* __restrict__ C, int ldc, int M, int N, int K)
{
    extern __shared__ __nv_bfloat16 sm[];
    const int tid = threadIdx.x, lane = tid & 31, warp = tid >> 5;
    const int warpM = (warp >> 1) * 32, warpN = (warp & 1) * 64;
    const int m0 = blockIdx.x * 128, n0 = blockIdx.y * 128;   // SWAPPED
    unsigned sbase = (unsigned)__cvta_generic_to_shared(sm);

    float acc[2][8][4];
    #pragma unroll
    for (int a = 0; a < 2; ++a)
        #pragma unroll
        for (int b = 0; b < 8; ++b)
            #pragma unroll
            for (int c = 0; c < 4; ++c) acc[a][b][c] = 0.f;

    const int cidx = tid & 7, rbase = tid >> 3;
    auto load_stage = [&](int s, int k0) {
        unsigned aB = sbase + (unsigned)s * 32768u;
        unsigned bB = aB + 16384u;
        #pragma unroll
        for (int j = 0; j < 4; ++j) {
            int r = j * 32 + rbase;
            const __nv_bfloat16* srcA = A + (size_t)(m0 + r) * lda + k0 + cidx * 8;
            int szA = (m0 + r < M) ? 16 : 0;
            asm volatile("cp.async.cg.shared.global [%0], [%1], 16, %2;\n"
                         :: "r"(aB + bswz(r, cidx) * 2u), "l"(srcA), "r"(szA));
            const __nv_bfloat16* srcB = B + (size_t)(n0 + r) * ldb + k0 + cidx * 8;
            asm volatile("cp.async.cg.shared.global [%0], [%1], 16, 16;\n"
                         :: "r"(bB + bswz(r, cidx) * 2u), "l"(srcB));
        }
        asm volatile("cp.async.commit_group;\n" ::);
    };
    auto compute = [&](int s) {
        unsigned aB = sbase + (unsigned)s * 32768u;
        unsigned bB = aB + 16384u;
        #pragma unroll
        for (int kk = 0; kk < 64; kk += 16) {
            unsigned af[2][4];
            #pragma unroll
            for (int mi = 0; mi < 2; ++mi) {
                int row = warpM + mi * 16 + (lane & 15);
                int ch = (kk >> 3) + (lane >> 4);
                LDSM4(af[mi], aB + bswz(row, ch) * 2u);
            }
            unsigned bf[4][4];
            #pragma unroll
            for (int ni = 0; ni < 4; ++ni) {
                int g = lane >> 3;
                int row = warpN + ni * 16 + ((g >> 1) << 3) + (lane & 7);
                int ch = (kk >> 3) + (g & 1);
                LDSM4(bf[ni], bB + bswz(row, ch) * 2u);
            }
            #pragma unroll
            for (int mi = 0; mi < 2; ++mi)
                #pragma unroll
                for (int n8 = 0; n8 < 8; ++n8) {
                    unsigned* bb = &bf[n8 >> 1][(n8 & 1) * 2];
                    MMA16816(acc[mi][n8], af[mi], bb[0], bb[1]);
                }
        }
    };

    const int KT = K >> 6;
    load_stage(0, 0);
    load_stage(1, 64);
    for (int t = 0; t < KT; ++t) {
        if (t + 2 < KT) {
            load_stage((t + 2) % 3, (t + 2) << 6);
            asm volatile("cp.async.wait_group 2;\n" ::);
        } else {
            asm volatile("cp.async.wait_group 0;\n" ::);
        }
        __syncthreads();
        compute(t % 3);
        __syncthreads();
    }

    #pragma unroll
    for (int mi = 0; mi < 2; ++mi) {
        int row = m0 + warpM + mi * 16 + (lane >> 2);
        #pragma unroll
        for (int n8 = 0; n8 < 8; ++n8) {
            int col = n0 + warpN + n8 * 8 + (lane & 3) * 2;
            if (row < M)
                *(float2*)(C + (size_t)row * ldc + col) =
                    make_float2(acc[mi][n8][0], acc[mi][n8][1]);
            if (row + 8 < M)
                *(float2*)(C + (size_t)(row + 8) * ldc + col) =
                    make_float2(acc[mi][n8][2], acc[mi][n8][3]);
        }
    }
}

// ---------------- top-64 coarse -> exact fp32 rescore -> top-32 + z ----------
__global__ __launch_bounds__(256) void topk_kernel(
    const float* __restrict__ scores, const float* __restrict__ u,
    const float* __restrict__ mem, float* __restrict__ z)
{
    extern __shared__ float dyn[];
    float* sv = dyn;
    float* us = dyn + M_;
    __shared__ float warpv[8];
    __shared__ int   warpi[8];
    __shared__ int   s_wini;
    __shared__ int   cand[64];
    __shared__ float scE[64];
    __shared__ float pw[KSEL];
    __shared__ int   pidx[KSEL];

    const int row = blockIdx.x, tid = threadIdx.x;
    const int lane = tid & 31, warp = tid >> 5;
    const float* sr = scores + (size_t)row * M_;
    const float* ur = u + (size_t)row * D_;

    float bv = -INFINITY; int bi = 0;
    #pragma unroll 4
    for (int j = 0; j < M_ / 256; ++j) {
        int i = tid + j * 256;
        float v = __ldcs(&sr[i]);
        sv[i] = v;
        if (v > bv) { bv = v; bi = i; }
    }
    for (int j = tid; j < D_; j += 256) us[j] = ur[j];
    __syncthreads();

    for (int sel = 0; sel < 64; ++sel) {
        float v = bv; int ix = bi;
        #pragma unroll
        for (int o = 16; o > 0; o >>= 1) {
            float v2 = __shfl_down_sync(0xffffffffu, v, o);
            int   i2 = __shfl_down_sync(0xffffffffu, ix, o);
            if (v2 > v || (v2 == v && i2 < ix)) { v = v2; ix = i2; }
        }
        if (lane == 0) { warpv[warp] = v; warpi[warp] = ix; }
        __syncthreads();
        if (warp == 0) {
            float v3 = (lane < 8) ? warpv[lane] : -INFINITY;
            int   i3 = (lane < 8) ? warpi[lane] : 0x7fffffff;
            #pragma unroll
            for (int o = 4; o > 0; o >>= 1) {
                float v2 = __shfl_down_sync(0xffffffffu, v3, o);
                int   i2 = __shfl_down_sync(0xffffffffu, i3, o);
                if (v2 > v3 || (v2 == v3 && i2 < i3)) { v3 = v2; i3 = i2; }
            }
            if (lane == 0) { s_wini = i3; cand[sel] = i3; }
        }
        __syncthreads();
        int w = s_wini;
        if ((w & 255) == tid) {
            sv[w] = -INFINITY;
            bv = -INFINITY; bi = 0;
            #pragma unroll 4
            for (int j = 0; j < M_ / 256; ++j) {
                int i = tid + j * 256;
                float vv = sv[i];
                if (vv > bv) { bv = vv; bi = i; }
            }
        }
        __syncthreads();
    }

    for (int r8 = 0; r8 < 8; ++r8) {
        int c = r8 * 8 + warp;
        const float* mr = mem + (size_t)cand[c] * D_;
        float s = 0.f;
        #pragma unroll 8
        for (int j = lane; j < D_; j += 32) s += us[j] * mr[j];
        #pragma unroll
        for (int o = 16; o > 0; o >>= 1) s += __shfl_down_sync(0xffffffffu, s, o);
        if (lane == 0) scE[c] = s;
    }
    __syncthreads();

    if (warp == 0) {
        float v0 = scE[lane], v1 = scE[32 + lane];
        int   i0 = cand[lane], i1 = cand[32 + lane];
        for (int s = 0; s < KSEL; ++s) {
            float v; int ix, slot;
            if (v0 > v1 || (v0 == v1 && i0 < i1)) { v = v0; ix = i0; slot = lane; }
            else                                  { v = v1; ix = i1; slot = 32 + lane; }
            #pragma unroll
            for (int o = 16; o > 0; o >>= 1) {
                float v2 = __shfl_down_sync(0xffffffffu, v, o);
                int   x2 = __shfl_down_sync(0xffffffffu, ix, o);
                int   s2 = __shfl_down_sync(0xffffffffu, slot, o);
                if (v2 > v || (v2 == v && x2 < ix)) { v = v2; ix = x2; slot = s2; }
            }
            v    = __shfl_sync(0xffffffffu, v, 0);
            ix   = __shfl_sync(0xffffffffu, ix, 0);
            slot = __shfl_sync(0xffffffffu, slot, 0);
            if (slot == lane)      v0 = -INFINITY;
            if (slot == 32 + lane) v1 = -INFINITY;
            if (lane == 0) { pw[s] = v; pidx[s] = ix; }
        }
        if (lane == 0) {
            float mx = pw[0], ssum = 0.f;
            for (int k = 0; k < KSEL; ++k) {
                float e = expf((pw[k] - mx) * 0.0625f);
                pw[k] = e; ssum += e;
            }
            float inv = 1.f / ssum;
            for (int k = 0; k < KSEL; ++k) pw[k] *= inv;
        }
    }
    __syncthreads();

    for (int d = tid; d < D_; d += 256) {
        float acc = 0.f;
        #pragma unroll
        for (int k = 0; k < KSEL; ++k) acc += pw[k] * mem[(size_t)pidx[k] * D_ + d];
        z[(size_t)row * D_ + d] = acc;
    }
}

// ---------------- head: exact fp32 warp-per-output dot ------------------------
__global__ void head_kernel(const float* __restrict__ fus, const float* __restrict__ hw,
                            const float* __restrict__ hb, float* __restrict__ out)
{
    int gw = (blockIdx.x * blockDim.x + threadIdx.x) >> 5;
    int lane = threadIdx.x & 31;
    if (gw >= B_ * C_) return;
    int b = gw / C_, c = gw % C_;
    const float4* fr = (const float4*)(fus + (size_t)b * D_);
    const float4* wr = (const float4*)(hw + (size_t)c * D_);
    float s = 0.f;
    #pragma unroll 4
    for (int j = lane; j < D_ / 4; j += 32) {
        float4 f = fr[j], w = wr[j];
        s += f.x * w.x + f.y * w.y + f.z * w.z + f.w * w.w;
    }
    #pragma unroll
    for (int o = 16; o > 0; o >>= 1) s += __shfl_down_sync(0xffffffffu, s, o);
    if (lane == 0) out[b * C_ + c] = s + hb[c];
}

// ---------------- launch --------------------------------------------------------
extern "C" void kernel_launch(void* const* d_in, const int* in_sizes, int n_in,
                              void* d_out, int out_size)
{
    const float* x      = (const float*)d_in[0];
    const float* mem    = (const float*)d_in[2];
    const float* ff_w   = (const float*)d_in[3];
    const float* ff_b   = (const float*)d_in[4];
    const float* mp_w   = (const float*)d_in[5];
    const float* mp_b   = (const float*)d_in[6];
    const float* wq     = (const float*)d_in[7];
    const float* bq     = (const float*)d_in[8];
    const float* wk     = (const float*)d_in[9];
    const float* wv     = (const float*)d_in[11];
    const float* bv     = (const float*)d_in[12];
    const float* wo     = (const float*)d_in[13];
    const float* bo     = (const float*)d_in[14];
    const float* fuse_w = (const float*)d_in[15];
    const float* fuse_b = (const float*)d_in[16];
    const float* head_w = (const float*)d_in[17];
    const float* head_b = (const float*)d_in[18];
    float* out = (float*)d_out;

    float *xm, *t, *u, *sc, *z, *fin, *fus, *part, *wkT, *mpwT;
    __nv_bfloat16 *u_bf, *mem_bf;
    cudaGetSymbolAddress((void**)&xm,   g_xm);
    cudaGetSymbolAddress((void**)&t,    g_t);
    cudaGetSymbolAddress((void**)&u,    g_u);
    cudaGetSymbolAddress((void**)&sc,   g_sc);
    cudaGetSymbolAddress((void**)&z,    g_z);
    cudaGetSymbolAddress((void**)&fin,  g_fin);
    cudaGetSymbolAddress((void**)&fus,  g_fus);
    cudaGetSymbolAddress((void**)&part, g_part);
    cudaGetSymbolAddress((void**)&wkT,  g_wkT);
    cudaGetSymbolAddress((void**)&mpwT, g_mpwT);
    cudaGetSymbolAddress((void**)&u_bf,   g_u_bf);
    cudaGetSymbolAddress((void**)&mem_bf, g_mem_bf);

    cudaFuncSetAttribute((const void*)bgemm3_kernel<3,8,64,1>,  cudaFuncAttributeMaxDynamicSharedMemorySize, 49152);
    cudaFuncSetAttribute((const void*)bgemm3_kernel<3,8,64,8>,  cudaFuncAttributeMaxDynamicSharedMemorySize, 49152);
    cudaFuncSetAttribute((const void*)bgemm3_kernel<3,1,64,8>,  cudaFuncAttributeMaxDynamicSharedMemorySize, 49152);
    cudaFuncSetAttribute((const void*)bgemm3_kernel<3,2,128,1>, cudaFuncAttributeMaxDynamicSharedMemorySize, 65536);
    cudaFuncSetAttribute((const void*)bgemm3_kernel<1,2,128,1>, cudaFuncAttributeMaxDynamicSharedMemorySize, 32768);
    cudaFuncSetAttribute((const void*)bgemm3_kernel<1,4,64,2>,  cudaFuncAttributeMaxDynamicSharedMemorySize, 24576);
    cudaFuncSetAttribute((const void*)bgemm3_kernel<1,8,64,4>,  cudaFuncAttributeMaxDynamicSharedMemorySize, 24576);
    cudaFuncSetAttribute((const void*)bgemm_kernel, cudaFuncAttributeMaxDynamicSharedMemorySize, 98304);
    cudaFuncSetAttribute((const void*)topk_kernel, cudaFuncAttributeMaxDynamicSharedMemorySize, (M_ + D_) * 4);

    const long long BD  = (long long)B_ * D_;
    const long long BHD = (long long)B_ * H_ * D_;

    // prep: transposes + mem bf16
    transpose_kernel<<<dim3(64, 64), dim3(32, 8)>>>(wk, wkT);
    transpose_kernel<<<dim3(64, 64), dim3(32, 8)>>>(mp_w, mpwT);
    f2b_kernel<<<8192, 256>>>(mem, mem_bf, M_ * D_);

    // 1) xm = mean_s(x)
    mean1_kernel<<<dim3(2, B_, 4), 256>>>(x, part);
    mean2_kernel<<<B_ * D_ / 1024, 256>>>(part, xm);

    // 2) xf partials: xm @ ff_w^T -> part0 (8 planes)
    bgemm3_kernel<3,8,64,1><<<dim3(16, 1, 8), 256, 49152>>>(
        xm, D_, 0, 0, nullptr, 0, ff_w, D_, 0,
        part + PART0, D_, 0, BD, B_, D_, D_);

    // 3) q partials: (Σ xf_part + ff_b) @ wq^T -> part1 (8 planes)
    bgemm3_kernel<3,8,64,8><<<dim3(16, 1, 8), 256, 49152>>>(
        part + PART0, D_, 0, BD, ff_b, 0, wq, D_, 0,
        part + PART1, D_, 0, BD, B_, D_, D_);

    // 4) fin[:, :D] = xf (reduce part0 + ff_b)
    reduce_kernel<0,false><<<dim3(512, 1), 256>>>(
        part + PART0, fin, 2 * D_, ff_b, nullptr, B_ * D_, D_, 8);

    // 5) t = (Σ q_part + bq)_h @ wk_h (TN via wkT; head offset = 256 COLUMNS)
    bgemm3_kernel<3,1,64,8><<<dim3(16, 1, H_), 256, 49152>>>(
        part + PART1, D_, DK_, BD, bq, DK_, wkT, D_, (long long)DK_,
        t, H_ * D_, D_, 0, B_, D_, DK_);

    // 6) u partials: t @ mp_w (TN via mpwT), split-K 2 -> part0; reduce emits u_bf
    bgemm3_kernel<3,2,128,1><<<dim3(16, 4, 2), 256, 65536>>>(
        t, D_, 0, 0, nullptr, 0, mpwT, D_, 0,
        part + PART0, D_, 0, BHD, B_ * H_, D_, D_);
    reduce_kernel<0,true><<<dim3(4096, 1), 256>>>(
        part + PART0, u, D_, nullptr, u_bf, B_ * H_ * D_, D_, 2);

    // 7) scores = u @ mem^T (bf16 TC, 3-stage; m-tiles fastest -> mem L2 reuse)
    bgemm_kernel<<<dim3(4, M_ / 128), 256, 98304>>>(
        u_bf, D_, mem_bf, D_, sc, M_, B_ * H_, M_, D_);

    // 8) topk -> z
    topk_kernel<<<B_ * H_, 256, (M_ + D_) * 4>>>(sc, u, mem, z);

    // 9) y partials: z @ mp_w^T, split-K 2 -> part0
    bgemm3_kernel<1,2,128,1><<<dim3(16, 4, 2), 256, 32768>>>(
        z, D_, 0, 0, nullptr, 0, mp_w, D_, 0,
        part + PART0, D_, 0, BHD, B_ * H_, D_, D_);

    // 10) attn partials: (Σ y_part + mp_b)_h @ wv_h^T, split-K 4 -> part2
    bgemm3_kernel<1,4,64,2><<<dim3(2, 1, H_ * 4), 256, 24576>>>(
        part + PART0, H_ * D_, D_, BHD, mp_b, 0, wv, D_, (long long)DK_ * D_,
        part + PART2, D_, DK_, BD, B_, DK_, D_);

    // 11) resp partials: (Σ attn_part + bv) @ wo^T, split-K 8 -> part0
    bgemm3_kernel<1,8,64,4><<<dim3(16, 1, 8), 256, 24576>>>(
        part + PART2, D_, 0, BD, bv, 0, wo, D_, 0,
        part + PART0, D_, 0, BD, B_, D_, D_);

    // 12) fin[:, D:] = resp (reduce part0 + bo)
    reduce_kernel<0,false><<<dim3(512, 1), 256>>>(
        part + PART0, fin + D_, 2 * D_, bo, nullptr, B_ * D_, D_, 8);

    // 13) fus = gelu((fin @ fuse_w^T) + fuse_b), split-K 8 -> part1
    bgemm3_kernel<3,8,64,1><<<dim3(16, 1, 8), 256, 49152>>>(
        fin, 2 * D_, 0, 0, nullptr, 0, fuse_w, 2 * D_, 0,
        part + PART1, D_, 0, BD, B_, D_, 2 * D_);
    reduce_kernel<1,false><<<dim3(512, 1), 256>>>(
        part + PART1, fus, D_, fuse_b, nullptr, B_ * D_, D_, 8);

    // 14) logits (exact fp32)
    head_kernel<<<(B_ * C_ * 32 + 255) / 256, 256>>>(fus, head_w, head_b, out);
}

// round 9
// speedup vs baseline: 1.2112x; 1.1457x over previous
#include <cuda_runtime.h>
#include <cuda_bf16.h>
#include <math.h>

#define B_  64
#define S_  196
#define D_  2048
#define H_  8
#define DK_ 256
#define M_  16384
#define KSEL 32
#define C_  29

__device__ float g_t  [B_ * H_ * D_];
__device__ float g_u  [B_ * H_ * D_];
__device__ float g_sc [B_ * H_ * M_];
__device__ float g_z  [B_ * H_ * D_];
__device__ float g_fin[B_ * 2 * D_];
__device__ float g_fus[B_ * D_];
__device__ float g_part[4 * 512 * 2048];   // 16 MB scratch, region-multiplexed
__device__ float g_wkT [D_ * D_];
__device__ float g_mpwT[D_ * D_];
__device__ __nv_bfloat16 g_u_bf [B_ * H_ * D_];
__device__ __nv_bfloat16 g_mem_bf[M_ * D_];

#define PART0 0
#define PART1 (1024 * 1024)      // +4 MB (in floats)
#define PART2 (2 * 1024 * 1024)  // +8 MB

__device__ __forceinline__ float gelu_exact(float v) {
    return 0.5f * v * (1.0f + erff(v * 0.70710678118654752f));
}
__device__ __forceinline__ void split2(float a, float b, unsigned& hi, unsigned& lo) {
    __nv_bfloat162 h = __floats2bfloat162_rn(a, b);
    __nv_bfloat162 l = __floats2bfloat162_rn(a - __bfloat162float(h.x),
                                             b - __bfloat162float(h.y));
    hi = *(unsigned*)&h; lo = *(unsigned*)&l;
}

#define LDSM4(R, ADDR) asm volatile( \
    "ldmatrix.sync.aligned.m8n8.x4.shared.b16 {%0,%1,%2,%3}, [%4];" \
    : "=r"((R)[0]), "=r"((R)[1]), "=r"((R)[2]), "=r"((R)[3]) : "r"(ADDR))
#define MMA16816(D, A, B0, B1) asm volatile( \
    "mma.sync.aligned.m16n8k16.row.col.f32.bf16.bf16.f32 " \
    "{%0,%1,%2,%3},{%4,%5,%6,%7},{%8,%9},{%0,%1,%2,%3};" \
    : "+f"((D)[0]), "+f"((D)[1]), "+f"((D)[2]), "+f"((D)[3]) \
    : "r"((A)[0]), "r"((A)[1]), "r"((A)[2]), "r"((A)[3]), "r"(B0), "r"(B1))

// ---------------- transpose fp32 DxD ----------------
__global__ void transpose_kernel(const float* __restrict__ in, float* __restrict__ out) {
    __shared__ float tile[32][33];
    int x = blockIdx.x * 32 + threadIdx.x;
    #pragma unroll
    for (int j = threadIdx.y; j < 32; j += 8)
        tile[j][threadIdx.x] = __ldcs(&in[(size_t)(blockIdx.y * 32 + j) * D_ + x]);
    __syncthreads();
    int xo = blockIdx.y * 32 + threadIdx.x;
    #pragma unroll
    for (int j = threadIdx.y; j < 32; j += 8)
        out[(size_t)(blockIdx.x * 32 + j) * D_ + xo] = tile[threadIdx.x][j];
}

// ---------------- fp32 -> bf16, streaming, 16 elems/thread ----------------
__global__ void f2b_kernel(const float* __restrict__ a, __nv_bfloat16* __restrict__ o, int n) {
    int stride = gridDim.x * blockDim.x * 16;
    for (int i = (blockIdx.x * blockDim.x + threadIdx.x) * 16; i < n; i += stride) {
        float4 v0 = __ldcs((const float4*)(a + i));
        float4 v1 = __ldcs((const float4*)(a + i + 4));
        float4 v2 = __ldcs((const float4*)(a + i + 8));
        float4 v3 = __ldcs((const float4*)(a + i + 12));
        __nv_bfloat162 r[8];
        r[0] = __floats2bfloat162_rn(v0.x, v0.y);
        r[1] = __floats2bfloat162_rn(v0.z, v0.w);
        r[2] = __floats2bfloat162_rn(v1.x, v1.y);
        r[3] = __floats2bfloat162_rn(v1.z, v1.w);
        r[4] = __floats2bfloat162_rn(v2.x, v2.y);
        r[5] = __floats2bfloat162_rn(v2.z, v2.w);
        r[6] = __floats2bfloat162_rn(v3.x, v3.y);
        r[7] = __floats2bfloat162_rn(v3.z, v3.w);
        __stcs((uint4*)(o + i),     *(uint4*)&r[0]);
        __stcs((uint4*)(o + i + 8), *(uint4*)&r[4]);
    }
}

// ---------------- mean over S: phase 1 (partials; phase 2 fused into xf GEMM) --
#define SCHUNK 49
__global__ void mean1_kernel(const float* __restrict__ x, float* __restrict__ part) {
    int d4 = blockIdx.x * 256 + threadIdx.x;
    int b = blockIdx.y;
    int sc = blockIdx.z;
    const float4* xp = (const float4*)(x + (size_t)b * S_ * D_) + (size_t)(sc * SCHUNK) * (D_ / 4) + d4;
    float4 s = make_float4(0.f, 0.f, 0.f, 0.f);
    #pragma unroll 7
    for (int i = 0; i < SCHUNK; ++i) {
        float4 v = __ldcs(xp + (size_t)i * (D_ / 4));
        s.x += v.x; s.y += v.y; s.z += v.z; s.w += v.w;
    }
    ((float4*)(part + ((size_t)sc * B_ + b) * D_))[d4] = s;
}

// ---------------- unified TC TN GEMM, fp32 in/out, in-reg bf16 ----------------
// C = scale * (Σ_{s<SPLITA} A_s + Abias) @ B^T.  NSPLIT 3 = hi/lo split.
template<int NSPLIT, int SPLITK, int BM, int SPLITA, int ASCALE>
__global__ __launch_bounds__(256) void bgemm3_kernel(
    const float* __restrict__ A, int lda, long long sAz, long long sAs,
    const float* __restrict__ Abias, int sAbz,
    const float* __restrict__ Bm, int ldb, long long sBz,
    float* __restrict__ C, int ldc, long long sCz, long long sCs,
    int M, int N, int K)
{
    extern __shared__ __nv_bfloat16 sm[];
    constexpr int APLANE = BM * 32;
    constexpr int LO_OFF = APLANE + 4096;
    constexpr int STAGE  = LO_OFF * ((NSPLIT == 3) ? 2 : 1);
    constexpr int N8     = (BM == 128) ? 8 : 4;
    const int tid = threadIdx.x, lane = tid & 31, warp = tid >> 5;
    const int warpM = (BM == 128) ? (warp >> 1) * 32 : (warp >> 2) * 32;
    const int warpN = (BM == 128) ? (warp & 1) * 64 : (warp & 3) * 32;
    const int m0 = blockIdx.y * BM;
    const int n0 = blockIdx.x * 128;
    const int zb = blockIdx.z / SPLITK, sk = blockIdx.z % SPLITK;
    const int Kc = K / SPLITK, k0base = sk * Kc;

    A  += (size_t)zb * sAz;
    Bm += (size_t)zb * sBz;
    C  += (size_t)zb * sCz + (size_t)sk * sCs;

    const int cc = tid & 7, rr = tid >> 3;
    float4 ra[BM / 32], rb[4];
    unsigned sbase = (unsigned)__cvta_generic_to_shared(sm);

    float acc[2][N8][4];
    #pragma unroll
    for (int a = 0; a < 2; ++a)
        #pragma unroll
        for (int b = 0; b < N8; ++b)
            #pragma unroll
            for (int c = 0; c < 4; ++c) acc[a][b][c] = 0.f;

    auto ldg = [&](int kt) {
        int kcol = k0base + kt * 32 + cc * 4;
        #pragma unroll
        for (int j = 0; j < BM / 32; ++j) {
            int rA = m0 + j * 32 + rr;
            float4 v = make_float4(0.f, 0.f, 0.f, 0.f);
            if (rA < M) {
                v = *(const float4*)(A + (size_t)rA * lda + kcol);
                #pragma unroll
                for (int s = 1; s < SPLITA; ++s) {
                    float4 w = *(const float4*)(A + (size_t)s * sAs + (size_t)rA * lda + kcol);
                    v.x += w.x; v.y += w.y; v.z += w.z; v.w += w.w;
                }
                if (Abias) {
                    float4 bb = *(const float4*)(Abias + (size_t)zb * sAbz + kcol);
                    v.x += bb.x; v.y += bb.y; v.z += bb.z; v.w += bb.w;
                }
                if (ASCALE) {
                    const float inv = 1.0f / S_;
                    v.x *= inv; v.y *= inv; v.z *= inv; v.w *= inv;
                }
            }
            ra[j] = v;
        }
        #pragma unroll
        for (int j = 0; j < 4; ++j) {
            int rB = n0 + j * 32 + rr;
            rb[j] = (rB < N) ? *(const float4*)(Bm + (size_t)rB * ldb + kcol)
                             : make_float4(0.f, 0.f, 0.f, 0.f);
        }
    };
    auto sts = [&](int s) {
        __nv_bfloat16* base = sm + s * STAGE;
        unsigned h0, h1, l0, l1;
        #pragma unroll
        for (int j = 0; j < BM / 32; ++j) {
            int row = j * 32 + rr;
            int off = row * 32 + ((((cc >> 1) ^ ((row >> 1) & 3)) << 3)) + ((cc & 1) << 2);
            split2(ra[j].x, ra[j].y, h0, l0);
            split2(ra[j].z, ra[j].w, h1, l1);
            *(uint2*)(base + off) = make_uint2(h0, h1);
            if (NSPLIT == 3) *(uint2*)(base + LO_OFF + off) = make_uint2(l0, l1);
        }
        #pragma unroll
        for (int j = 0; j < 4; ++j) {
            int row = j * 32 + rr;
            int off = APLANE + row * 32 + ((((cc >> 1) ^ ((row >> 1) & 3)) << 3)) + ((cc & 1) << 2);
            split2(rb[j].x, rb[j].y, h0, l0);
            split2(rb[j].z, rb[j].w, h1, l1);
            *(uint2*)(base + off) = make_uint2(h0, h1);
            if (NSPLIT == 3) *(uint2*)(base + LO_OFF + off) = make_uint2(l0, l1);
        }
    };
    auto compute = [&](int s) {
        unsigned aB = sbase + (unsigned)(s * STAGE) * 2u;
        unsigned bB = aB + (unsigned)APLANE * 2u;
        #pragma unroll
        for (int kk = 0; kk < 32; kk += 16) {
            unsigned ah[2][4], al[2][4];
            #pragma unroll
            for (int mi = 0; mi < 2; ++mi) {
                int row = warpM + mi * 16 + (lane & 15);
                int ch = (kk >> 3) + (lane >> 4);
                unsigned addr = aB +
                    (unsigned)(row * 32 + ((ch ^ ((row >> 1) & 3)) << 3)) * 2u;
                LDSM4(ah[mi], addr);
                if (NSPLIT == 3) LDSM4(al[mi], addr + (unsigned)LO_OFF * 2u);
            }
            unsigned bh[N8 / 2][4], bl[N8 / 2][4];
            #pragma unroll
            for (int ni = 0; ni < N8 / 2; ++ni) {
                int g = lane >> 3;
                int row = warpN + ni * 16 + ((g >> 1) << 3) + (lane & 7);
                int ch = (kk >> 3) + (g & 1);
                unsigned addr = bB +
                    (unsigned)(row * 32 + ((ch ^ ((row >> 1) & 3)) << 3)) * 2u;
                LDSM4(bh[ni], addr);
                if (NSPLIT == 3) LDSM4(bl[ni], addr + (unsigned)LO_OFF * 2u);
            }
            #pragma unroll
            for (int mi = 0; mi < 2; ++mi)
                #pragma unroll
                for (int n8 = 0; n8 < N8; ++n8) {
                    unsigned* hb = &bh[n8 >> 1][(n8 & 1) * 2];
                    MMA16816(acc[mi][n8], ah[mi], hb[0], hb[1]);
                    if (NSPLIT == 3) {
                        unsigned* lb = &bl[n8 >> 1][(n8 & 1) * 2];
                        MMA16816(acc[mi][n8], ah[mi], lb[0], lb[1]);
                        MMA16816(acc[mi][n8], al[mi], hb[0], hb[1]);
                    }
                }
        }
    };

    const int KT = Kc / 32;
    ldg(0);
    sts(0);
    __syncthreads();
    for (int t = 0; t < KT; ++t) {
        if (t + 1 < KT) ldg(t + 1);
        compute(t & 1);
        __syncthreads();
        if (t + 1 < KT) { sts((t + 1) & 1); __syncthreads(); }
    }

    #pragma unroll
    for (int mi = 0; mi < 2; ++mi) {
        int row = m0 + warpM + mi * 16 + (lane >> 2);
        #pragma unroll
        for (int n8 = 0; n8 < N8; ++n8) {
            int col = n0 + warpN + n8 * 8 + (lane & 3) * 2;
            if (row < M)
                *(float2*)(C + (size_t)row * ldc + col) =
                    make_float2(acc[mi][n8][0], acc[mi][n8][1]);
            if (row + 8 < M)
                *(float2*)(C + (size_t)(row + 8) * ldc + col) =
                    make_float2(acc[mi][n8][2], acc[mi][n8][3]);
        }
    }
}

// ---------------- split-K reduce (+bias, +gelu, +bf16 mirror) ----------------
template<int EPI, bool WBF>
__global__ void reduce_kernel(const float* __restrict__ part, float* __restrict__ C,
                              int ldc, const float* __restrict__ bias,
                              __nv_bfloat16* __restrict__ Cbf,
                              int MN, int N, int SPLIT)
{
    int i = blockIdx.x * 256 + threadIdx.x;
    if (i >= MN) return;
    const float* p = part + i;
    float s = 0.f;
    for (int k = 0; k < SPLIT; ++k) s += p[(size_t)k * MN];
    int n = i % N;
    if (bias) s += bias[n];
    if (EPI == 1) s = gelu_exact(s);
    C[(size_t)(i / N) * ldc + n] = s;
    if (WBF) Cbf[i] = __float2bfloat16(s);
}

// ---------------- scores: bf16 TC TN GEMM, 3-stage cp.async -------------------
__device__ __forceinline__ unsigned bswz(int row, int chunk) {
    return (unsigned)(row * 64 + ((chunk ^ (row & 7)) * 8));
}
__global__ __launch_bounds__(256) void bgemm_kernel(
    const __nv_bfloat16* __restrict__ A, int lda,
    const __nv_bfloat16* __restrict__ B, int ldb,
    float* __restrict__ C, int ldc, int M, int N, int K)
{
    extern __shared__ __nv_bfloat16 sm[];
    const int tid = threadIdx.x, lane = tid & 31, warp = tid >> 5;
    const int warpM = (warp >> 1) * 32, warpN = (warp & 1) * 64;
    const int m0 = blockIdx.x * 128, n0 = blockIdx.y * 128;   // m fastest: B-tile L2 reuse
    unsigned sbase = (unsigned)__cvta_generic_to_shared(sm);

    float acc[2][8][4];
    #pragma unroll
    for (int a = 0; a < 2; ++a)
        #pragma unroll
        for (int b = 0; b < 8; ++b)
            #pragma unroll
            for (int c = 0; c < 4; ++c) acc[a][b][c] = 0.f;

    const int cidx = tid & 7, rbase = tid >> 3;
    auto load_stage = [&](int s, int k0) {
        unsigned aB = sbase + (unsigned)s * 32768u;
        unsigned bB = aB + 16384u;
        #pragma unroll
        for (int j = 0; j < 4; ++j) {
            int r = j * 32 + rbase;
            const __nv_bfloat16* srcA = A + (size_t)(m0 + r) * lda + k0 + cidx * 8;
            int szA = (m0 + r < M) ? 16 : 0;
            asm volatile("cp.async.cg.shared.global [%0], [%1], 16, %2;\n"
                         :: "r"(aB + bswz(r, cidx) * 2u), "l"(srcA), "r"(szA));
            const __nv_bfloat16* srcB = B + (size_t)(n0 + r) * ldb + k0 + cidx * 8;
            asm volatile("cp.async.cg.shared.global [%0], [%1], 16, 16;\n"
                         :: "r"(bB + bswz(r, cidx) * 2u), "l"(srcB));
        }
        asm volatile("cp.async.commit_group;\n" ::);
    };
    auto compute = [&](int s) {
        unsigned aB = sbase + (unsigned)s * 32768u;
        unsigned bB = aB + 16384u;
        #pragma unroll
        for (int kk = 0; kk < 64; kk += 16) {
            unsigned af[2][4];
            #pragma unroll
            for (int mi = 0; mi < 2; ++mi) {
                int row = warpM + mi * 16 + (lane & 15);
                int ch = (kk >> 3) + (lane >> 4);
                LDSM4(af[mi], aB + bswz(row, ch) * 2u);
            }
            unsigned bf[4][4];
            #pragma unroll
            for (int ni = 0; ni < 4; ++ni) {
                int g = lane >> 3;
                int row = warpN + ni * 16 + ((g >> 1) << 3) + (lane & 7);
                int ch = (kk >> 3) + (g & 1);
                LDSM4(bf[ni], bB + bswz(row, ch) * 2u);
            }
            #pragma unroll
            for (int mi = 0; mi < 2; ++mi)
                #pragma unroll
                for (int n8 = 0; n8 < 8; ++n8) {
                    unsigned* bb = &bf[n8 >> 1][(n8 & 1) * 2];
                    MMA16816(acc[mi][n8], af[mi], bb[0], bb[1]);
                }
        }
    };

    const int KT = K >> 6;
    load_stage(0, 0);
    load_stage(1, 64);
    for (int t = 0; t < KT; ++t) {
        if (t + 2 < KT) {
            load_stage((t + 2) % 3, (t + 2) << 6);
            asm volatile("cp.async.wait_group 2;\n" ::);
        } else {
            asm volatile("cp.async.wait_group 0;\n" ::);
        }
        __syncthreads();
        compute(t % 3);
        __syncthreads();
    }

    #pragma unroll
    for (int mi = 0; mi < 2; ++mi) {
        int row = m0 + warpM + mi * 16 + (lane >> 2);
        #pragma unroll
        for (int n8 = 0; n8 < 8; ++n8) {
            int col = n0 + warpN + n8 * 8 + (lane & 3) * 2;
            if (row < M)
                *(float2*)(C + (size_t)row * ldc + col) =
                    make_float2(acc[mi][n8][0], acc[mi][n8][1]);
            if (row + 8 < M)
                *(float2*)(C + (size_t)(row + 8) * ldc + col) =
                    make_float2(acc[mi][n8][2], acc[mi][n8][3]);
        }
    }
}

// ---------------- topk: sync-free per-warp top-32 -> 8-way merge -> z ---------
// Per-warp top-32 over its 2048-slice (union provably contains global top-32),
// then warp 0 merges the 8 sorted lists. Softmax over selected bf16-GEMM scores.
__global__ __launch_bounds__(256) void topk_kernel(
    const float* __restrict__ scores, const float* __restrict__ mem,
    float* __restrict__ z)
{
    extern __shared__ float sv[];            // M_ floats
    __shared__ float wvv[8 * KSEL];
    __shared__ int   wii[8 * KSEL];
    __shared__ float pw[KSEL];
    __shared__ int   pidx[KSEL];

    const int row = blockIdx.x, tid = threadIdx.x;
    const int lane = tid & 31, warp = tid >> 5;
    const float* sr = scores + (size_t)row * M_;

    #pragma unroll 4
    for (int j = 0; j < M_ / 256; ++j) {
        int i = tid + j * 256;
        sv[i] = __ldcs(&sr[i]);
    }
    __syncthreads();

    // per-warp top-32 (sorted desc, ties -> lower index), no block syncs
    const int base = warp * (M_ / 8);
    float bv = -INFINITY; int bi = base + lane;
    #pragma unroll 4
    for (int j = 0; j < M_ / 256; ++j) {
        int idx = base + lane + j * 32;
        float v = sv[idx];
        if (v > bv) { bv = v; bi = idx; }
    }
    for (int sel = 0; sel < KSEL; ++sel) {
        float v = bv; int ix = bi;
        #pragma unroll
        for (int o = 16; o > 0; o >>= 1) {
            float v2 = __shfl_down_sync(0xffffffffu, v, o);
            int   i2 = __shfl_down_sync(0xffffffffu, ix, o);
            if (v2 > v || (v2 == v && i2 < ix)) { v = v2; ix = i2; }
        }
        v  = __shfl_sync(0xffffffffu, v, 0);
        ix = __shfl_sync(0xffffffffu, ix, 0);
        if (lane == 0) { wvv[warp * KSEL + sel] = v; wii[warp * KSEL + sel] = ix; }
        if (((ix - base) & 31) == lane) {
            sv[ix] = -INFINITY;
            bv = -INFINITY; bi = base + lane;
            #pragma unroll 4
            for (int j = 0; j < M_ / 256; ++j) {
                int idx = base + lane + j * 32;
                float vv = sv[idx];
                if (vv > bv) { bv = vv; bi = idx; }
            }
        }
    }
    __syncthreads();

    // merge 8 sorted lists (lanes 0..7 carry heads); exact global top-32
    if (warp == 0) {
        bool act = lane < 8;
        int head = 0;
        float cv = act ? wvv[lane * KSEL] : -INFINITY;
        int   ci = act ? wii[lane * KSEL] : 0x7fffffff;
        for (int sel = 0; sel < KSEL; ++sel) {
            float v = cv; int ix = ci; int src = lane;
            #pragma unroll
            for (int o = 16; o > 0; o >>= 1) {
                float v2 = __shfl_down_sync(0xffffffffu, v, o);
                int   i2 = __shfl_down_sync(0xffffffffu, ix, o);
                int   s2 = __shfl_down_sync(0xffffffffu, src, o);
                if (v2 > v || (v2 == v && i2 < ix)) { v = v2; ix = i2; src = s2; }
            }
            v   = __shfl_sync(0xffffffffu, v, 0);
            ix  = __shfl_sync(0xffffffffu, ix, 0);
            src = __shfl_sync(0xffffffffu, src, 0);
            if (lane == 0) { pw[sel] = v; pidx[sel] = ix; }
            if (lane == src) {
                ++head;
                cv = (head < KSEL) ? wvv[lane * KSEL + head] : -INFINITY;
                ci = (head < KSEL) ? wii[lane * KSEL + head] : 0x7fffffff;
            }
        }
        if (lane == 0) {
            float mx = pw[0], ssum = 0.f;
            for (int k = 0; k < KSEL; ++k) {
                float e = expf((pw[k] - mx) * 0.0625f);
                pw[k] = e; ssum += e;
            }
            float inv = 1.f / ssum;
            for (int k = 0; k < KSEL; ++k) pw[k] *= inv;
        }
    }
    __syncthreads();

    for (int d = tid; d < D_; d += 256) {
        float acc = 0.f;
        #pragma unroll
        for (int k = 0; k < KSEL; ++k) acc += pw[k] * mem[(size_t)pidx[k] * D_ + d];
        z[(size_t)row * D_ + d] = acc;
    }
}

// ---------------- head: exact fp32 warp-per-output dot ------------------------
__global__ void head_kernel(const float* __restrict__ fus, const float* __restrict__ hw,
                            const float* __restrict__ hb, float* __restrict__ out)
{
    int gw = (blockIdx.x * blockDim.x + threadIdx.x) >> 5;
    int lane = threadIdx.x & 31;
    if (gw >= B_ * C_) return;
    int b = gw / C_, c = gw % C_;
    const float4* fr = (const float4*)(fus + (size_t)b * D_);
    const float4* wr = (const float4*)(hw + (size_t)c * D_);
    float s = 0.f;
    #pragma unroll 4
    for (int j = lane; j < D_ / 4; j += 32) {
        float4 f = fr[j], w = wr[j];
        s += f.x * w.x + f.y * w.y + f.z * w.z + f.w * w.w;
    }
    #pragma unroll
    for (int o = 16; o > 0; o >>= 1) s += __shfl_down_sync(0xffffffffu, s, o);
    if (lane == 0) out[b * C_ + c] = s + hb[c];
}

// ---------------- launch --------------------------------------------------------
extern "C" void kernel_launch(void* const* d_in, const int* in_sizes, int n_in,
                              void* d_out, int out_size)
{
    const float* x      = (const float*)d_in[0];
    const float* mem    = (const float*)d_in[2];
    const float* ff_w   = (const float*)d_in[3];
    const float* ff_b   = (const float*)d_in[4];
    const float* mp_w   = (const float*)d_in[5];
    const float* mp_b   = (const float*)d_in[6];
    const float* wq     = (const float*)d_in[7];
    const float* bq     = (const float*)d_in[8];
    const float* wk     = (const float*)d_in[9];
    const float* wv     = (const float*)d_in[11];
    const float* bv     = (const float*)d_in[12];
    const float* wo     = (const float*)d_in[13];
    const float* bo     = (const float*)d_in[14];
    const float* fuse_w = (const float*)d_in[15];
    const float* fuse_b = (const float*)d_in[16];
    const float* head_w = (const float*)d_in[17];
    const float* head_b = (const float*)d_in[18];
    float* out = (float*)d_out;

    float *t, *u, *sc, *z, *fin, *fus, *part, *wkT, *mpwT;
    __nv_bfloat16 *u_bf, *mem_bf;
    cudaGetSymbolAddress((void**)&t,    g_t);
    cudaGetSymbolAddress((void**)&u,    g_u);
    cudaGetSymbolAddress((void**)&sc,   g_sc);
    cudaGetSymbolAddress((void**)&z,    g_z);
    cudaGetSymbolAddress((void**)&fin,  g_fin);
    cudaGetSymbolAddress((void**)&fus,  g_fus);
    cudaGetSymbolAddress((void**)&part, g_part);
    cudaGetSymbolAddress((void**)&wkT,  g_wkT);
    cudaGetSymbolAddress((void**)&mpwT, g_mpwT);
    cudaGetSymbolAddress((void**)&u_bf,   g_u_bf);
    cudaGetSymbolAddress((void**)&mem_bf, g_mem_bf);

    cudaFuncSetAttribute((const void*)bgemm3_kernel<3,8,64,4,1>,  cudaFuncAttributeMaxDynamicSharedMemorySize, 49152);
    cudaFuncSetAttribute((const void*)bgemm3_kernel<3,8,64,8,0>,  cudaFuncAttributeMaxDynamicSharedMemorySize, 49152);
    cudaFuncSetAttribute((const void*)bgemm3_kernel<3,1,64,8,0>,  cudaFuncAttributeMaxDynamicSharedMemorySize, 49152);
    cudaFuncSetAttribute((const void*)bgemm3_kernel<3,2,128,1,0>, cudaFuncAttributeMaxDynamicSharedMemorySize, 65536);
    cudaFuncSetAttribute((const void*)bgemm3_kernel<1,2,128,1,0>, cudaFuncAttributeMaxDynamicSharedMemorySize, 32768);
    cudaFuncSetAttribute((const void*)bgemm3_kernel<1,4,64,2,0>,  cudaFuncAttributeMaxDynamicSharedMemorySize, 24576);
    cudaFuncSetAttribute((const void*)bgemm3_kernel<1,8,64,4,0>,  cudaFuncAttributeMaxDynamicSharedMemorySize, 24576);
    cudaFuncSetAttribute((const void*)bgemm3_kernel<3,8,64,1,0>,  cudaFuncAttributeMaxDynamicSharedMemorySize, 49152);
    cudaFuncSetAttribute((const void*)bgemm_kernel, cudaFuncAttributeMaxDynamicSharedMemorySize, 98304);
    cudaFuncSetAttribute((const void*)topk_kernel, cudaFuncAttributeMaxDynamicSharedMemorySize, M_ * 4);

    const long long BD  = (long long)B_ * D_;
    const long long BHD = (long long)B_ * H_ * D_;

    // prep: transposes + mem bf16
    transpose_kernel<<<dim3(64, 64), dim3(32, 8)>>>(wk, wkT);
    transpose_kernel<<<dim3(64, 64), dim3(32, 8)>>>(mp_w, mpwT);
    f2b_kernel<<<8192, 256>>>(mem, mem_bf, M_ * D_);

    // 1) mean partials -> PART2 (4 planes of B_*D_)
    mean1_kernel<<<dim3(2, B_, 4), 256>>>(x, part + PART2);

    // 2) xf partials: mean(x) @ ff_w^T -> part0 (8 planes); mean fused via SPLITA=4+scale
    bgemm3_kernel<3,8,64,4,1><<<dim3(16, 1, 8), 256, 49152>>>(
        part + PART2, D_, 0, BD, nullptr, 0, ff_w, D_, 0,
        part + PART0, D_, 0, BD, B_, D_, D_);

    // 3) q partials: (Σ xf_part + ff_b) @ wq^T -> part1 (8 planes)
    bgemm3_kernel<3,8,64,8,0><<<dim3(16, 1, 8), 256, 49152>>>(
        part + PART0, D_, 0, BD, ff_b, 0, wq, D_, 0,
        part + PART1, D_, 0, BD, B_, D_, D_);

    // 4) fin[:, :D] = xf (reduce part0 + ff_b)
    reduce_kernel<0,false><<<dim3(512, 1), 256>>>(
        part + PART0, fin, 2 * D_, ff_b, nullptr, B_ * D_, D_, 8);

    // 5) t = (Σ q_part + bq)_h @ wk_h (TN via wkT; head offset = 256 COLUMNS)
    bgemm3_kernel<3,1,64,8,0><<<dim3(16, 1, H_), 256, 49152>>>(
        part + PART1, D_, DK_, BD, bq, DK_, wkT, D_, (long long)DK_,
        t, H_ * D_, D_, 0, B_, D_, DK_);

    // 6) u partials: t @ mp_w (TN via mpwT), split-K 2 -> part0; reduce emits u_bf
    bgemm3_kernel<3,2,128,1,0><<<dim3(16, 4, 2), 256, 65536>>>(
        t, D_, 0, 0, nullptr, 0, mpwT, D_, 0,
        part + PART0, D_, 0, BHD, B_ * H_, D_, D_);
    reduce_kernel<0,true><<<dim3(4096, 1), 256>>>(
        part + PART0, u, D_, nullptr, u_bf, B_ * H_ * D_, D_, 2);

    // 7) scores = u @ mem^T (bf16 TC, 3-stage; m-tiles fastest -> mem L2 reuse)
    bgemm_kernel<<<dim3(4, M_ / 128), 256, 98304>>>(
        u_bf, D_, mem_bf, D_, sc, M_, B_ * H_, M_, D_);

    // 8) topk (bf16-score selection, no rescore) -> z
    topk_kernel<<<B_ * H_, 256, M_ * 4>>>(sc, mem, z);

    // 9) y partials: z @ mp_w^T, split-K 2 -> part0
    bgemm3_kernel<1,2,128,1,0><<<dim3(16, 4, 2), 256, 32768>>>(
        z, D_, 0, 0, nullptr, 0, mp_w, D_, 0,
        part + PART0, D_, 0, BHD, B_ * H_, D_, D_);

    // 10) attn partials: (Σ y_part + mp_b)_h @ wv_h^T, split-K 4 -> part2
    bgemm3_kernel<1,4,64,2,0><<<dim3(2, 1, H_ * 4), 256, 24576>>>(
        part + PART0, H_ * D_, D_, BHD, mp_b, 0, wv, D_, (long long)DK_ * D_,
        part + PART2, D_, DK_, BD, B_, DK_, D_);

    // 11) resp partials: (Σ attn_part + bv) @ wo^T, split-K 8 -> part0
    bgemm3_kernel<1,8,64,4,0><<<dim3(16, 1, 8), 256, 24576>>>(
        part + PART2, D_, 0, BD, bv, 0, wo, D_, 0,
        part + PART0, D_, 0, BD, B_, D_, D_);

    // 12) fin[:, D:] = resp (reduce part0 + bo)
    reduce_kernel<0,false><<<dim3(512, 1), 256>>>(
        part + PART0, fin + D_, 2 * D_, bo, nullptr, B_ * D_, D_, 8);

    // 13) fus = gelu((fin @ fuse_w^T) + fuse_b), split-K 8 -> part1
    bgemm3_kernel<3,8,64,1,0><<<dim3(16, 1, 8), 256, 49152>>>(
        fin, 2 * D_, 0, 0, nullptr, 0, fuse_w, 2 * D_, 0,
        part + PART1, D_, 0, BD, B_, D_, 2 * D_);
    reduce_kernel<1,false><<<dim3(512, 1), 256>>>(
        part + PART1, fus, D_, fuse_b, nullptr, B_ * D_, D_, 8);

    // 14) logits (exact fp32)
    head_kernel<<<(B_ * C_ * 32 + 255) / 256, 256>>>(fus, head_w, head_b, out);
}

// round 11
// speedup vs baseline: 1.4530x; 1.1997x over previous
#include <cuda_runtime.h>
#include <cuda_bf16.h>
#include <math.h>

#define B_  64
#define S_  196
#define D_  2048
#define H_  8
#define DK_ 256
#define M_  16384
#define KSEL 32
#define C_  29

__device__ float g_t  [B_ * H_ * D_];
__device__ float g_u  [B_ * H_ * D_];
__device__ float g_z  [B_ * H_ * D_];
__device__ float g_fin[B_ * 2 * D_];
__device__ float g_fus[B_ * D_];
__device__ float g_part[4 * 512 * 2048];   // 16 MB scratch, region-multiplexed
__device__ float g_wkT [D_ * D_];
__device__ float g_mpwT[D_ * D_];
__device__ __nv_bfloat16 g_u_bf [B_ * H_ * D_];
__device__ __nv_bfloat16 g_mem_bf[M_ * D_];
__device__ __nv_bfloat16 g_sc_bf[B_ * H_ * M_];   // 16 MB

#define PART0 0
#define PART1 (1024 * 1024)      // +4 MB (in floats)
#define PART2 (2 * 1024 * 1024)  // +8 MB

__device__ __forceinline__ float gelu_exact(float v) {
    return 0.5f * v * (1.0f + erff(v * 0.70710678118654752f));
}
__device__ __forceinline__ void split2(float a, float b, unsigned& hi, unsigned& lo) {
    __nv_bfloat162 h = __floats2bfloat162_rn(a, b);
    __nv_bfloat162 l = __floats2bfloat162_rn(a - __bfloat162float(h.x),
                                             b - __bfloat162float(h.y));
    hi = *(unsigned*)&h; lo = *(unsigned*)&l;
}

#define LDSM4(R, ADDR) asm volatile( \
    "ldmatrix.sync.aligned.m8n8.x4.shared.b16 {%0,%1,%2,%3}, [%4];" \
    : "=r"((R)[0]), "=r"((R)[1]), "=r"((R)[2]), "=r"((R)[3]) : "r"(ADDR))
#define MMA16816(D, A, B0, B1) asm volatile( \
    "mma.sync.aligned.m16n8k16.row.col.f32.bf16.bf16.f32 " \
    "{%0,%1,%2,%3},{%4,%5,%6,%7},{%8,%9},{%0,%1,%2,%3};" \
    : "+f"((D)[0]), "+f"((D)[1]), "+f"((D)[2]), "+f"((D)[3]) \
    : "r"((A)[0]), "r"((A)[1]), "r"((A)[2]), "r"((A)[3]), "r"(B0), "r"(B1))

// ---------------- transpose fp32 DxD ----------------
__global__ void transpose_kernel(const float* __restrict__ in, float* __restrict__ out) {
    __shared__ float tile[32][33];
    int x = blockIdx.x * 32 + threadIdx.x;
    #pragma unroll
    for (int j = threadIdx.y; j < 32; j += 8)
        tile[j][threadIdx.x] = __ldcs(&in[(size_t)(blockIdx.y * 32 + j) * D_ + x]);
    __syncthreads();
    int xo = blockIdx.y * 32 + threadIdx.x;
    #pragma unroll
    for (int j = threadIdx.y; j < 32; j += 8)
        out[(size_t)(blockIdx.x * 32 + j) * D_ + xo] = tile[threadIdx.x][j];
}

// ---------------- fp32 -> bf16, streaming ----------------
__global__ void f2b_kernel(const float* __restrict__ a, __nv_bfloat16* __restrict__ o, int n) {
    int stride = gridDim.x * blockDim.x * 16;
    for (int i = (blockIdx.x * blockDim.x + threadIdx.x) * 16; i < n; i += stride) {
        float4 v0 = __ldcs((const float4*)(a + i));
        float4 v1 = __ldcs((const float4*)(a + i + 4));
        float4 v2 = __ldcs((const float4*)(a + i + 8));
        float4 v3 = __ldcs((const float4*)(a + i + 12));
        __nv_bfloat162 r[8];
        r[0] = __floats2bfloat162_rn(v0.x, v0.y);
        r[1] = __floats2bfloat162_rn(v0.z, v0.w);
        r[2] = __floats2bfloat162_rn(v1.x, v1.y);
        r[3] = __floats2bfloat162_rn(v1.z, v1.w);
        r[4] = __floats2bfloat162_rn(v2.x, v2.y);
        r[5] = __floats2bfloat162_rn(v2.z, v2.w);
        r[6] = __floats2bfloat162_rn(v3.x, v3.y);
        r[7] = __floats2bfloat162_rn(v3.z, v3.w);
        __stcs((uint4*)(o + i),     *(uint4*)&r[0]);
        __stcs((uint4*)(o + i + 8), *(uint4*)&r[4]);
    }
}

// ---------------- mean over S: phase 1 (7 chunks of 28) ----------------
#define SCHUNK 28
__global__ void mean1_kernel(const float* __restrict__ x, float* __restrict__ part) {
    int d4 = blockIdx.x * 256 + threadIdx.x;
    int b = blockIdx.y;
    int sc = blockIdx.z;
    const float4* xp = (const float4*)(x + (size_t)b * S_ * D_) + (size_t)(sc * SCHUNK) * (D_ / 4) + d4;
    float4 s = make_float4(0.f, 0.f, 0.f, 0.f);
    #pragma unroll 7
    for (int i = 0; i < SCHUNK; ++i) {
        float4 v = __ldcs(xp + (size_t)i * (D_ / 4));
        s.x += v.x; s.y += v.y; s.z += v.z; s.w += v.w;
    }
    ((float4*)(part + ((size_t)sc * B_ + b) * D_))[d4] = s;
}

// ---------------- unified TC TN GEMM, fp32 in/out, in-reg bf16 ----------------
template<int NSPLIT, int SPLITK, int BM, int SPLITA, int ASCALE>
__global__ __launch_bounds__(256) void bgemm3_kernel(
    const float* __restrict__ A, int lda, long long sAz, long long sAs,
    const float* __restrict__ Abias, int sAbz,
    const float* __restrict__ Bm, int ldb, long long sBz,
    float* __restrict__ C, int ldc, long long sCz, long long sCs,
    int M, int N, int K)
{
    extern __shared__ __nv_bfloat16 sm[];
    constexpr int APLANE = BM * 32;
    constexpr int LO_OFF = APLANE + 4096;
    constexpr int STAGE  = LO_OFF * ((NSPLIT == 3) ? 2 : 1);
    constexpr int N8     = (BM == 128) ? 8 : 4;
    const int tid = threadIdx.x, lane = tid & 31, warp = tid >> 5;
    const int warpM = (BM == 128) ? (warp >> 1) * 32 : (warp >> 2) * 32;
    const int warpN = (BM == 128) ? (warp & 1) * 64 : (warp & 3) * 32;
    const int m0 = blockIdx.y * BM;
    const int n0 = blockIdx.x * 128;
    const int zb = blockIdx.z / SPLITK, sk = blockIdx.z % SPLITK;
    const int Kc = K / SPLITK, k0base = sk * Kc;

    A  += (size_t)zb * sAz;
    Bm += (size_t)zb * sBz;
    C  += (size_t)zb * sCz + (size_t)sk * sCs;

    const int cc = tid & 7, rr = tid >> 3;
    float4 ra[BM / 32], rb[4];
    unsigned sbase = (unsigned)__cvta_generic_to_shared(sm);

    float acc[2][N8][4];
    #pragma unroll
    for (int a = 0; a < 2; ++a)
        #pragma unroll
        for (int b = 0; b < N8; ++b)
            #pragma unroll
            for (int c = 0; c < 4; ++c) acc[a][b][c] = 0.f;

    auto ldg = [&](int kt) {
        int kcol = k0base + kt * 32 + cc * 4;
        #pragma unroll
        for (int j = 0; j < BM / 32; ++j) {
            int rA = m0 + j * 32 + rr;
            float4 v = make_float4(0.f, 0.f, 0.f, 0.f);
            if (rA < M) {
                v = *(const float4*)(A + (size_t)rA * lda + kcol);
                #pragma unroll
                for (int s = 1; s < SPLITA; ++s) {
                    float4 w = *(const float4*)(A + (size_t)s * sAs + (size_t)rA * lda + kcol);
                    v.x += w.x; v.y += w.y; v.z += w.z; v.w += w.w;
                }
                if (Abias) {
                    float4 bb = *(const float4*)(Abias + (size_t)zb * sAbz + kcol);
                    v.x += bb.x; v.y += bb.y; v.z += bb.z; v.w += bb.w;
                }
                if (ASCALE) {
                    const float inv = 1.0f / S_;
                    v.x *= inv; v.y *= inv; v.z *= inv; v.w *= inv;
                }
            }
            ra[j] = v;
        }
        #pragma unroll
        for (int j = 0; j < 4; ++j) {
            int rB = n0 + j * 32 + rr;
            rb[j] = (rB < N) ? *(const float4*)(Bm + (size_t)rB * ldb + kcol)
                             : make_float4(0.f, 0.f, 0.f, 0.f);
        }
    };
    auto sts = [&](int s) {
        __nv_bfloat16* base = sm + s * STAGE;
        unsigned h0, h1, l0, l1;
        #pragma unroll
        for (int j = 0; j < BM / 32; ++j) {
            int row = j * 32 + rr;
            int off = row * 32 + ((((cc >> 1) ^ ((row >> 1) & 3)) << 3)) + ((cc & 1) << 2);
            split2(ra[j].x, ra[j].y, h0, l0);
            split2(ra[j].z, ra[j].w, h1, l1);
            *(uint2*)(base + off) = make_uint2(h0, h1);
            if (NSPLIT == 3) *(uint2*)(base + LO_OFF + off) = make_uint2(l0, l1);
        }
        #pragma unroll
        for (int j = 0; j < 4; ++j) {
            int row = j * 32 + rr;
            int off = APLANE + row * 32 + ((((cc >> 1) ^ ((row >> 1) & 3)) << 3)) + ((cc & 1) << 2);
            split2(rb[j].x, rb[j].y, h0, l0);
            split2(rb[j].z, rb[j].w, h1, l1);
            *(uint2*)(base + off) = make_uint2(h0, h1);
            if (NSPLIT == 3) *(uint2*)(base + LO_OFF + off) = make_uint2(l0, l1);
        }
    };
    auto compute = [&](int s) {
        unsigned aB = sbase + (unsigned)(s * STAGE) * 2u;
        unsigned bB = aB + (unsigned)APLANE * 2u;
        #pragma unroll
        for (int kk = 0; kk < 32; kk += 16) {
            unsigned ah[2][4], al[2][4];
            #pragma unroll
            for (int mi = 0; mi < 2; ++mi) {
                int row = warpM + mi * 16 + (lane & 15);
                int ch = (kk >> 3) + (lane >> 4);
                unsigned addr = aB +
                    (unsigned)(row * 32 + ((ch ^ ((row >> 1) & 3)) << 3)) * 2u;
                LDSM4(ah[mi], addr);
                if (NSPLIT == 3) LDSM4(al[mi], addr + (unsigned)LO_OFF * 2u);
            }
            unsigned bh[N8 / 2][4], bl[N8 / 2][4];
            #pragma unroll
            for (int ni = 0; ni < N8 / 2; ++ni) {
                int g = lane >> 3;
                int row = warpN + ni * 16 + ((g >> 1) << 3) + (lane & 7);
                int ch = (kk >> 3) + (g & 1);
                unsigned addr = bB +
                    (unsigned)(row * 32 + ((ch ^ ((row >> 1) & 3)) << 3)) * 2u;
                LDSM4(bh[ni], addr);
                if (NSPLIT == 3) LDSM4(bl[ni], addr + (unsigned)LO_OFF * 2u);
            }
            #pragma unroll
            for (int mi = 0; mi < 2; ++mi)
                #pragma unroll
                for (int n8 = 0; n8 < N8; ++n8) {
                    unsigned* hb = &bh[n8 >> 1][(n8 & 1) * 2];
                    MMA16816(acc[mi][n8], ah[mi], hb[0], hb[1]);
                    if (NSPLIT == 3) {
                        unsigned* lb = &bl[n8 >> 1][(n8 & 1) * 2];
                        MMA16816(acc[mi][n8], ah[mi], lb[0], lb[1]);
                        MMA16816(acc[mi][n8], al[mi], hb[0], hb[1]);
                    }
                }
        }
    };

    const int KT = Kc / 32;
    ldg(0);
    sts(0);
    __syncthreads();
    for (int t = 0; t < KT; ++t) {
        if (t + 1 < KT) ldg(t + 1);
        compute(t & 1);
        __syncthreads();
        if (t + 1 < KT) { sts((t + 1) & 1); __syncthreads(); }
    }

    #pragma unroll
    for (int mi = 0; mi < 2; ++mi) {
        int row = m0 + warpM + mi * 16 + (lane >> 2);
        #pragma unroll
        for (int n8 = 0; n8 < N8; ++n8) {
            int col = n0 + warpN + n8 * 8 + (lane & 3) * 2;
            if (row < M)
                *(float2*)(C + (size_t)row * ldc + col) =
                    make_float2(acc[mi][n8][0], acc[mi][n8][1]);
            if (row + 8 < M)
                *(float2*)(C + (size_t)(row + 8) * ldc + col) =
                    make_float2(acc[mi][n8][2], acc[mi][n8][3]);
        }
    }
}

// ---------------- split-K reduce (+bias, +gelu, +bf16 mirror) ----------------
template<int EPI, bool WBF>
__global__ void reduce_kernel(const float* __restrict__ part, float* __restrict__ C,
                              int ldc, const float* __restrict__ bias,
                              __nv_bfloat16* __restrict__ Cbf,
                              int MN, int N, int SPLIT)
{
    int i = blockIdx.x * 256 + threadIdx.x;
    if (i >= MN) return;
    const float* p = part + i;
    float s = 0.f;
    for (int k = 0; k < SPLIT; ++k) s += p[(size_t)k * MN];
    int n = i % N;
    if (bias) s += bias[n];
    if (EPI == 1) s = gelu_exact(s);
    C[(size_t)(i / N) * ldc + n] = s;
    if (WBF) Cbf[i] = __float2bfloat16(s);
}

// ---------------- scores: bf16 TC TN GEMM, 3-stage cp.async, bf16 out ---------
__device__ __forceinline__ unsigned bswz(int row, int chunk) {
    return (unsigned)(row * 64 + ((chunk ^ (row & 7)) * 8));
}
__global__ __launch_bounds__(256) void bgemm_kernel(
    const __nv_bfloat16* __restrict__ A, int lda,
    const __nv_bfloat16* __restrict__ B, int ldb,
    __nv_bfloat16* __restrict__ C, int ldc, int M, int N, int K)
{
    extern __shared__ __nv_bfloat16 sm[];
    const int tid = threadIdx.x, lane = tid & 31, warp = tid >> 5;
    const int warpM = (warp >> 1) * 32, warpN = (warp & 1) * 64;
    const int m0 = blockIdx.x * 128, n0 = blockIdx.y * 128;   // m fastest: B-tile L2 reuse
    unsigned sbase = (unsigned)__cvta_generic_to_shared(sm);

    float acc[2][8][4];
    #pragma unroll
    for (int a = 0; a < 2; ++a)
        #pragma unroll
        for (int b = 0; b < 8; ++b)
            #pragma unroll
            for (int c = 0; c < 4; ++c) acc[a][b][c] = 0.f;

    const int cidx = tid & 7, rbase = tid >> 3;
    auto load_stage = [&](int s, int k0) {
        unsigned aB = sbase + (unsigned)s * 32768u;
        unsigned bB = aB + 16384u;
        #pragma unroll
        for (int j = 0; j < 4; ++j) {
            int r = j * 32 + rbase;
            const __nv_bfloat16* srcA = A + (size_t)(m0 + r) * lda + k0 + cidx * 8;
            int szA = (m0 + r < M) ? 16 : 0;
            asm volatile("cp.async.cg.shared.global [%0], [%1], 16, %2;\n"
                         :: "r"(aB + bswz(r, cidx) * 2u), "l"(srcA), "r"(szA));
            const __nv_bfloat16* srcB = B + (size_t)(n0 + r) * ldb + k0 + cidx * 8;
            asm volatile("cp.async.cg.shared.global [%0], [%1], 16, 16;\n"
                         :: "r"(bB + bswz(r, cidx) * 2u), "l"(srcB));
        }
        asm volatile("cp.async.commit_group;\n" ::);
    };
    auto compute = [&](int s) {
        unsigned aB = sbase + (unsigned)s * 32768u;
        unsigned bB = aB + 16384u;
        #pragma unroll
        for (int kk = 0; kk < 64; kk += 16) {
            unsigned af[2][4];
            #pragma unroll
            for (int mi = 0; mi < 2; ++mi) {
                int row = warpM + mi * 16 + (lane & 15);
                int ch = (kk >> 3) + (lane >> 4);
                LDSM4(af[mi], aB + bswz(row, ch) * 2u);
            }
            unsigned bf[4][4];
            #pragma unroll
            for (int ni = 0; ni < 4; ++ni) {
                int g = lane >> 3;
                int row = warpN + ni * 16 + ((g >> 1) << 3) + (lane & 7);
                int ch = (kk >> 3) + (g & 1);
                LDSM4(bf[ni], bB + bswz(row, ch) * 2u);
            }
            #pragma unroll
            for (int mi = 0; mi < 2; ++mi)
                #pragma unroll
                for (int n8 = 0; n8 < 8; ++n8) {
                    unsigned* bb = &bf[n8 >> 1][(n8 & 1) * 2];
                    MMA16816(acc[mi][n8], af[mi], bb[0], bb[1]);
                }
        }
    };

    const int KT = K >> 6;
    load_stage(0, 0);
    load_stage(1, 64);
    for (int t = 0; t < KT; ++t) {
        if (t + 2 < KT) {
            load_stage((t + 2) % 3, (t + 2) << 6);
            asm volatile("cp.async.wait_group 2;\n" ::);
        } else {
            asm volatile("cp.async.wait_group 0;\n" ::);
        }
        __syncthreads();
        compute(t % 3);
        __syncthreads();
    }

    #pragma unroll
    for (int mi = 0; mi < 2; ++mi) {
        int row = m0 + warpM + mi * 16 + (lane >> 2);
        #pragma unroll
        for (int n8 = 0; n8 < 8; ++n8) {
            int col = n0 + warpN + n8 * 8 + (lane & 3) * 2;
            if (row < M)
                *(__nv_bfloat162*)(C + (size_t)row * ldc + col) =
                    __floats2bfloat162_rn(acc[mi][n8][0], acc[mi][n8][1]);
            if (row + 8 < M)
                *(__nv_bfloat162*)(C + (size_t)(row + 8) * ldc + col) =
                    __floats2bfloat162_rn(acc[mi][n8][2], acc[mi][n8][3]);
        }
    }
}

// ---------------- topk: sync-free per-warp top-32 -> 8-way merge -> z ---------
// bf16 scores in; z gathered from bf16 mem (L2-hot after scores GEMM).
__global__ __launch_bounds__(256) void topk_kernel(
    const __nv_bfloat16* __restrict__ scores, const __nv_bfloat16* __restrict__ memb,
    float* __restrict__ z)
{
    extern __shared__ float sv[];            // M_ floats
    __shared__ float wvv[8 * KSEL];
    __shared__ int   wii[8 * KSEL];
    __shared__ float pw[KSEL];
    __shared__ int   pidx[KSEL];

    const int row = blockIdx.x, tid = threadIdx.x;
    const int lane = tid & 31, warp = tid >> 5;
    const __nv_bfloat16* sr = scores + (size_t)row * M_;

    #pragma unroll
    for (int j = 0; j < M_ / (256 * 8); ++j) {
        int i8 = (tid + j * 256) * 8;
        uint4 q = __ldcs((const uint4*)(sr + i8));
        const __nv_bfloat162* h = (const __nv_bfloat162*)&q;
        #pragma unroll
        for (int e = 0; e < 4; ++e) {
            float2 f = __bfloat1622float2(h[e]);
            sv[i8 + e * 2]     = f.x;
            sv[i8 + e * 2 + 1] = f.y;
        }
    }
    __syncthreads();

    const int base = warp * (M_ / 8);
    float bv = -INFINITY; int bi = base + lane;
    #pragma unroll 4
    for (int j = 0; j < M_ / 256; ++j) {
        int idx = base + lane + j * 32;
        float v = sv[idx];
        if (v > bv) { bv = v; bi = idx; }
    }
    for (int sel = 0; sel < KSEL; ++sel) {
        float v = bv; int ix = bi;
        #pragma unroll
        for (int o = 16; o > 0; o >>= 1) {
            float v2 = __shfl_down_sync(0xffffffffu, v, o);
            int   i2 = __shfl_down_sync(0xffffffffu, ix, o);
            if (v2 > v || (v2 == v && i2 < ix)) { v = v2; ix = i2; }
        }
        v  = __shfl_sync(0xffffffffu, v, 0);
        ix = __shfl_sync(0xffffffffu, ix, 0);
        if (lane == 0) { wvv[warp * KSEL + sel] = v; wii[warp * KSEL + sel] = ix; }
        if (((ix - base) & 31) == lane) {
            sv[ix] = -INFINITY;
            bv = -INFINITY; bi = base + lane;
            #pragma unroll 4
            for (int j = 0; j < M_ / 256; ++j) {
                int idx = base + lane + j * 32;
                float vv = sv[idx];
                if (vv > bv) { bv = vv; bi = idx; }
            }
        }
    }
    __syncthreads();

    if (warp == 0) {
        bool act = lane < 8;
        int head = 0;
        float cv = act ? wvv[lane * KSEL] : -INFINITY;
        int   ci = act ? wii[lane * KSEL] : 0x7fffffff;
        for (int sel = 0; sel < KSEL; ++sel) {
            float v = cv; int ix = ci; int src = lane;
            #pragma unroll
            for (int o = 16; o > 0; o >>= 1) {
                float v2 = __shfl_down_sync(0xffffffffu, v, o);
                int   i2 = __shfl_down_sync(0xffffffffu, ix, o);
                int   s2 = __shfl_down_sync(0xffffffffu, src, o);
                if (v2 > v || (v2 == v && i2 < ix)) { v = v2; ix = i2; src = s2; }
            }
            v   = __shfl_sync(0xffffffffu, v, 0);
            ix  = __shfl_sync(0xffffffffu, ix, 0);
            src = __shfl_sync(0xffffffffu, src, 0);
            if (lane == 0) { pw[sel] = v; pidx[sel] = ix; }
            if (lane == src) {
                ++head;
                cv = (head < KSEL) ? wvv[lane * KSEL + head] : -INFINITY;
                ci = (head < KSEL) ? wii[lane * KSEL + head] : 0x7fffffff;
            }
        }
        if (lane == 0) {
            float mx = pw[0], ssum = 0.f;
            for (int k = 0; k < KSEL; ++k) {
                float e = expf((pw[k] - mx) * 0.0625f);
                pw[k] = e; ssum += e;
            }
            float inv = 1.f / ssum;
            for (int k = 0; k < KSEL; ++k) pw[k] *= inv;
        }
    }
    __syncthreads();

    // z gather from bf16 mem (vectorized: 8 elems per thread)
    {
        int d0 = tid * 8;
        float av[8];
        #pragma unroll
        for (int e = 0; e < 8; ++e) av[e] = 0.f;
        #pragma unroll 4
        for (int k = 0; k < KSEL; ++k) {
            float p = pw[k];
            uint4 q = *(const uint4*)(memb + (size_t)pidx[k] * D_ + d0);
            const __nv_bfloat162* h = (const __nv_bfloat162*)&q;
            #pragma unroll
            for (int e = 0; e < 4; ++e) {
                float2 f = __bfloat1622float2(h[e]);
                av[e * 2]     += p * f.x;
                av[e * 2 + 1] += p * f.y;
            }
        }
        float* dst = z + (size_t)row * D_ + d0;
        *(float4*)(dst)     = make_float4(av[0], av[1], av[2], av[3]);
        *(float4*)(dst + 4) = make_float4(av[4], av[5], av[6], av[7]);
    }
}

// ---------------- head: exact fp32 warp-per-output dot ------------------------
__global__ void head_kernel(const float* __restrict__ fus, const float* __restrict__ hw,
                            const float* __restrict__ hb, float* __restrict__ out)
{
    int gw = (blockIdx.x * blockDim.x + threadIdx.x) >> 5;
    int lane = threadIdx.x & 31;
    if (gw >= B_ * C_) return;
    int b = gw / C_, c = gw % C_;
    const float4* fr = (const float4*)(fus + (size_t)b * D_);
    const float4* wr = (const float4*)(hw + (size_t)c * D_);
    float s = 0.f;
    #pragma unroll 4
    for (int j = lane; j < D_ / 4; j += 32) {
        float4 f = fr[j], w = wr[j];
        s += f.x * w.x + f.y * w.y + f.z * w.z + f.w * w.w;
    }
    #pragma unroll
    for (int o = 16; o > 0; o >>= 1) s += __shfl_down_sync(0xffffffffu, s, o);
    if (lane == 0) out[b * C_ + c] = s + hb[c];
}

// ---------------- launch --------------------------------------------------------
extern "C" void kernel_launch(void* const* d_in, const int* in_sizes, int n_in,
                              void* d_out, int out_size)
{
    const float* x      = (const float*)d_in[0];
    const float* mem    = (const float*)d_in[2];
    const float* ff_w   = (const float*)d_in[3];
    const float* ff_b   = (const float*)d_in[4];
    const float* mp_w   = (const float*)d_in[5];
    const float* mp_b   = (const float*)d_in[6];
    const float* wq     = (const float*)d_in[7];
    const float* bq     = (const float*)d_in[8];
    const float* wk     = (const float*)d_in[9];
    const float* wv     = (const float*)d_in[11];
    const float* bv     = (const float*)d_in[12];
    const float* wo     = (const float*)d_in[13];
    const float* bo     = (const float*)d_in[14];
    const float* fuse_w = (const float*)d_in[15];
    const float* fuse_b = (const float*)d_in[16];
    const float* head_w = (const float*)d_in[17];
    const float* head_b = (const float*)d_in[18];
    float* out = (float*)d_out;

    float *t, *u, *z, *fin, *fus, *part, *wkT, *mpwT;
    __nv_bfloat16 *u_bf, *mem_bf, *sc_bf;
    cudaGetSymbolAddress((void**)&t,    g_t);
    cudaGetSymbolAddress((void**)&u,    g_u);
    cudaGetSymbolAddress((void**)&z,    g_z);
    cudaGetSymbolAddress((void**)&fin,  g_fin);
    cudaGetSymbolAddress((void**)&fus,  g_fus);
    cudaGetSymbolAddress((void**)&part, g_part);
    cudaGetSymbolAddress((void**)&wkT,  g_wkT);
    cudaGetSymbolAddress((void**)&mpwT, g_mpwT);
    cudaGetSymbolAddress((void**)&u_bf,   g_u_bf);
    cudaGetSymbolAddress((void**)&mem_bf, g_mem_bf);
    cudaGetSymbolAddress((void**)&sc_bf,  g_sc_bf);

    cudaFuncSetAttribute((const void*)bgemm3_kernel<3,8,64,7,1>,  cudaFuncAttributeMaxDynamicSharedMemorySize, 49152);
    cudaFuncSetAttribute((const void*)bgemm3_kernel<3,8,64,8,0>,  cudaFuncAttributeMaxDynamicSharedMemorySize, 49152);
    cudaFuncSetAttribute((const void*)bgemm3_kernel<3,1,64,8,0>,  cudaFuncAttributeMaxDynamicSharedMemorySize, 49152);
    cudaFuncSetAttribute((const void*)bgemm3_kernel<3,2,128,1,0>, cudaFuncAttributeMaxDynamicSharedMemorySize, 65536);
    cudaFuncSetAttribute((const void*)bgemm3_kernel<1,2,128,1,0>, cudaFuncAttributeMaxDynamicSharedMemorySize, 32768);
    cudaFuncSetAttribute((const void*)bgemm3_kernel<1,4,64,2,0>,  cudaFuncAttributeMaxDynamicSharedMemorySize, 24576);
    cudaFuncSetAttribute((const void*)bgemm3_kernel<1,8,64,4,0>,  cudaFuncAttributeMaxDynamicSharedMemorySize, 24576);
    cudaFuncSetAttribute((const void*)bgemm3_kernel<3,8,64,1,0>,  cudaFuncAttributeMaxDynamicSharedMemorySize, 49152);
    cudaFuncSetAttribute((const void*)bgemm_kernel, cudaFuncAttributeMaxDynamicSharedMemorySize, 98304);
    cudaFuncSetAttribute((const void*)topk_kernel, cudaFuncAttributeMaxDynamicSharedMemorySize, M_ * 4);

    const long long BD  = (long long)B_ * D_;
    const long long BHD = (long long)B_ * H_ * D_;

    // prep: transposes + mem bf16
    transpose_kernel<<<dim3(64, 64), dim3(32, 8)>>>(wk, wkT);
    transpose_kernel<<<dim3(64, 64), dim3(32, 8)>>>(mp_w, mpwT);
    f2b_kernel<<<8192, 256>>>(mem, mem_bf, M_ * D_);

    // 1) mean partials -> PART2 (7 planes of B_*D_)
    mean1_kernel<<<dim3(2, B_, 7), 256>>>(x, part + PART2);

    // 2) xf partials: mean(x) @ ff_w^T -> part0 (8 planes); mean fused via SPLITA=7+scale
    bgemm3_kernel<3,8,64,7,1><<<dim3(16, 1, 8), 256, 49152>>>(
        part + PART2, D_, 0, BD, nullptr, 0, ff_w, D_, 0,
        part + PART0, D_, 0, BD, B_, D_, D_);

    // 3) q partials: (Σ xf_part + ff_b) @ wq^T -> part1 (8 planes)
    bgemm3_kernel<3,8,64,8,0><<<dim3(16, 1, 8), 256, 49152>>>(
        part + PART0, D_, 0, BD, ff_b, 0, wq, D_, 0,
        part + PART1, D_, 0, BD, B_, D_, D_);

    // 4) fin[:, :D] = xf (reduce part0 + ff_b)
    reduce_kernel<0,false><<<dim3(512, 1), 256>>>(
        part + PART0, fin, 2 * D_, ff_b, nullptr, B_ * D_, D_, 8);

    // 5) t = (Σ q_part + bq)_h @ wk_h (TN via wkT; head offset = 256 COLUMNS)
    bgemm3_kernel<3,1,64,8,0><<<dim3(16, 1, H_), 256, 49152>>>(
        part + PART1, D_, DK_, BD, bq, DK_, wkT, D_, (long long)DK_,
        t, H_ * D_, D_, 0, B_, D_, DK_);

    // 6) u partials: t @ mp_w (TN via mpwT), split-K 2 -> part0; reduce emits u_bf
    bgemm3_kernel<3,2,128,1,0><<<dim3(16, 4, 2), 256, 65536>>>(
        t, D_, 0, 0, nullptr, 0, mpwT, D_, 0,
        part + PART0, D_, 0, BHD, B_ * H_, D_, D_);
    reduce_kernel<0,true><<<dim3(4096, 1), 256>>>(
        part + PART0, u, D_, nullptr, u_bf, B_ * H_ * D_, D_, 2);

    // 7) scores = u @ mem^T (bf16 TC, 3-stage; m fastest -> mem L2 reuse; bf16 out)
    bgemm_kernel<<<dim3(4, M_ / 128), 256, 98304>>>(
        u_bf, D_, mem_bf, D_, sc_bf, M_, B_ * H_, M_, D_);

    // 8) topk (bf16 scores) -> z (gather from bf16 mem)
    topk_kernel<<<B_ * H_, 256, M_ * 4>>>(sc_bf, mem_bf, z);

    // 9) y partials: z @ mp_w^T, split-K 2 -> part0
    bgemm3_kernel<1,2,128,1,0><<<dim3(16, 4, 2), 256, 32768>>>(
        z, D_, 0, 0, nullptr, 0, mp_w, D_, 0,
        part + PART0, D_, 0, BHD, B_ * H_, D_, D_);

    // 10) attn partials: (Σ y_part + mp_b)_h @ wv_h^T, split-K 4 -> part2
    bgemm3_kernel<1,4,64,2,0><<<dim3(2, 1, H_ * 4), 256, 24576>>>(
        part + PART0, H_ * D_, D_, BHD, mp_b, 0, wv, D_, (long long)DK_ * D_,
        part + PART2, D_, DK_, BD, B_, DK_, D_);

    // 11) resp partials: (Σ attn_part + bv) @ wo^T, split-K 8 -> part0
    bgemm3_kernel<1,8,64,4,0><<<dim3(16, 1, 8), 256, 24576>>>(
        part + PART2, D_, 0, BD, bv, 0, wo, D_, 0,
        part + PART0, D_, 0, BD, B_, D_, D_);

    // 12) fin[:, D:] = resp (reduce part0 + bo)
    reduce_kernel<0,false><<<dim3(512, 1), 256>>>(
        part + PART0, fin + D_, 2 * D_, bo, nullptr, B_ * D_, D_, 8);

    // 13) fus = gelu((fin @ fuse_w^T) + fuse_b), split-K 8 -> part1
    bgemm3_kernel<3,8,64,1,0><<<dim3(16, 1, 8), 256, 49152>>>(
        fin, 2 * D_, 0, 0, nullptr, 0, fuse_w, 2 * D_, 0,
        part + PART1, D_, 0, BD, B_, D_, 2 * D_);
    reduce_kernel<1,false><<<dim3(512, 1), 256>>>(
        part + PART1, fus, D_, fuse_b, nullptr, B_ * D_, D_, 8);

    // 14) logits (exact fp32)
    head_kernel<<<(B_ * C_ * 32 + 255) / 256, 256>>>(fus, head_w, head_b, out);
}

// round 12
// speedup vs baseline: 1.4930x; 1.0275x over previous
#include <cuda_runtime.h>
#include <cuda_bf16.h>
#include <math.h>

#define B_  64
#define S_  196
#define D_  2048
#define H_  8
#define DK_ 256
#define M_  16384
#define KSEL 32
#define C_  29

__device__ float g_t  [B_ * H_ * D_];
__device__ float g_u  [B_ * H_ * D_];
__device__ float g_z  [B_ * H_ * D_];
__device__ float g_fin[B_ * 2 * D_];
__device__ float g_fus[B_ * D_];
__device__ float g_part[4 * 512 * 2048];   // 16 MB scratch, region-multiplexed
__device__ float g_wkT [D_ * D_];
__device__ float g_mpwT[D_ * D_];
__device__ __nv_bfloat16 g_u_bf [B_ * H_ * D_];
__device__ __nv_bfloat16 g_mem_bf[M_ * D_];
__device__ __nv_bfloat16 g_sc_bf[B_ * H_ * M_];   // 16 MB

#define PART0 0
#define PART1 (1024 * 1024)      // +4 MB (in floats)
#define PART2 (2 * 1024 * 1024)  // +8 MB

__device__ __forceinline__ float gelu_exact(float v) {
    return 0.5f * v * (1.0f + erff(v * 0.70710678118654752f));
}
__device__ __forceinline__ void split2(float a, float b, unsigned& hi, unsigned& lo) {
    __nv_bfloat162 h = __floats2bfloat162_rn(a, b);
    __nv_bfloat162 l = __floats2bfloat162_rn(a - __bfloat162float(h.x),
                                             b - __bfloat162float(h.y));
    hi = *(unsigned*)&h; lo = *(unsigned*)&l;
}

#define LDSM4(R, ADDR) asm volatile( \
    "ldmatrix.sync.aligned.m8n8.x4.shared.b16 {%0,%1,%2,%3}, [%4];" \
    : "=r"((R)[0]), "=r"((R)[1]), "=r"((R)[2]), "=r"((R)[3]) : "r"(ADDR))
#define MMA16816(D, A, B0, B1) asm volatile( \
    "mma.sync.aligned.m16n8k16.row.col.f32.bf16.bf16.f32 " \
    "{%0,%1,%2,%3},{%4,%5,%6,%7},{%8,%9},{%0,%1,%2,%3};" \
    : "+f"((D)[0]), "+f"((D)[1]), "+f"((D)[2]), "+f"((D)[3]) \
    : "r"((A)[0]), "r"((A)[1]), "r"((A)[2]), "r"((A)[3]), "r"(B0), "r"(B1))

// ---------------- transpose fp32 DxD ----------------
__global__ void transpose_kernel(const float* __restrict__ in, float* __restrict__ out) {
    __shared__ float tile[32][33];
    int x = blockIdx.x * 32 + threadIdx.x;
    #pragma unroll
    for (int j = threadIdx.y; j < 32; j += 8)
        tile[j][threadIdx.x] = __ldcs(&in[(size_t)(blockIdx.y * 32 + j) * D_ + x]);
    __syncthreads();
    int xo = blockIdx.y * 32 + threadIdx.x;
    #pragma unroll
    for (int j = threadIdx.y; j < 32; j += 8)
        out[(size_t)(blockIdx.x * 32 + j) * D_ + xo] = tile[threadIdx.x][j];
}

// ---------------- fp32 -> bf16, streaming ----------------
__global__ void f2b_kernel(const float* __restrict__ a, __nv_bfloat16* __restrict__ o, int n) {
    int stride = gridDim.x * blockDim.x * 16;
    for (int i = (blockIdx.x * blockDim.x + threadIdx.x) * 16; i < n; i += stride) {
        float4 v0 = __ldcs((const float4*)(a + i));
        float4 v1 = __ldcs((const float4*)(a + i + 4));
        float4 v2 = __ldcs((const float4*)(a + i + 8));
        float4 v3 = __ldcs((const float4*)(a + i + 12));
        __nv_bfloat162 r[8];
        r[0] = __floats2bfloat162_rn(v0.x, v0.y);
        r[1] = __floats2bfloat162_rn(v0.z, v0.w);
        r[2] = __floats2bfloat162_rn(v1.x, v1.y);
        r[3] = __floats2bfloat162_rn(v1.z, v1.w);
        r[4] = __floats2bfloat162_rn(v2.x, v2.y);
        r[5] = __floats2bfloat162_rn(v2.z, v2.w);
        r[6] = __floats2bfloat162_rn(v3.x, v3.y);
        r[7] = __floats2bfloat162_rn(v3.z, v3.w);
        __stcs((uint4*)(o + i),     *(uint4*)&r[0]);
        __stcs((uint4*)(o + i + 8), *(uint4*)&r[4]);
    }
}

// ---------------- mean over S: phase 1 (7 chunks of 28) ----------------
#define SCHUNK 28
__global__ void mean1_kernel(const float* __restrict__ x, float* __restrict__ part) {
    int d4 = blockIdx.x * 256 + threadIdx.x;
    int b = blockIdx.y;
    int sc = blockIdx.z;
    const float4* xp = (const float4*)(x + (size_t)b * S_ * D_) + (size_t)(sc * SCHUNK) * (D_ / 4) + d4;
    float4 s = make_float4(0.f, 0.f, 0.f, 0.f);
    #pragma unroll 7
    for (int i = 0; i < SCHUNK; ++i) {
        float4 v = __ldcs(xp + (size_t)i * (D_ / 4));
        s.x += v.x; s.y += v.y; s.z += v.z; s.w += v.w;
    }
    ((float4*)(part + ((size_t)sc * B_ + b) * D_))[d4] = s;
}

// ---------------- unified TC TN GEMM, fp32 in/out, in-reg bf16 ----------------
template<int NSPLIT, int SPLITK, int BM, int SPLITA, int ASCALE>
__global__ __launch_bounds__(256) void bgemm3_kernel(
    const float* __restrict__ A, int lda, long long sAz, long long sAs,
    const float* __restrict__ Abias, int sAbz,
    const float* __restrict__ Bm, int ldb, long long sBz,
    float* __restrict__ C, int ldc, long long sCz, long long sCs,
    int M, int N, int K)
{
    extern __shared__ __nv_bfloat16 sm[];
    constexpr int APLANE = BM * 32;
    constexpr int LO_OFF = APLANE + 4096;
    constexpr int STAGE  = LO_OFF * ((NSPLIT == 3) ? 2 : 1);
    constexpr int N8     = (BM == 128) ? 8 : 4;
    const int tid = threadIdx.x, lane = tid & 31, warp = tid >> 5;
    const int warpM = (BM == 128) ? (warp >> 1) * 32 : (warp >> 2) * 32;
    const int warpN = (BM == 128) ? (warp & 1) * 64 : (warp & 3) * 32;
    const int m0 = blockIdx.y * BM;
    const int n0 = blockIdx.x * 128;
    const int zb = blockIdx.z / SPLITK, sk = blockIdx.z % SPLITK;
    const int Kc = K / SPLITK, k0base = sk * Kc;

    A  += (size_t)zb * sAz;
    Bm += (size_t)zb * sBz;
    C  += (size_t)zb * sCz + (size_t)sk * sCs;

    const int cc = tid & 7, rr = tid >> 3;
    float4 ra[BM / 32], rb[4];
    unsigned sbase = (unsigned)__cvta_generic_to_shared(sm);

    float acc[2][N8][4];
    #pragma unroll
    for (int a = 0; a < 2; ++a)
        #pragma unroll
        for (int b = 0; b < N8; ++b)
            #pragma unroll
            for (int c = 0; c < 4; ++c) acc[a][b][c] = 0.f;

    auto ldg = [&](int kt) {
        int kcol = k0base + kt * 32 + cc * 4;
        #pragma unroll
        for (int j = 0; j < BM / 32; ++j) {
            int rA = m0 + j * 32 + rr;
            float4 v = make_float4(0.f, 0.f, 0.f, 0.f);
            if (rA < M) {
                v = *(const float4*)(A + (size_t)rA * lda + kcol);
                #pragma unroll
                for (int s = 1; s < SPLITA; ++s) {
                    float4 w = *(const float4*)(A + (size_t)s * sAs + (size_t)rA * lda + kcol);
                    v.x += w.x; v.y += w.y; v.z += w.z; v.w += w.w;
                }
                if (Abias) {
                    float4 bb = *(const float4*)(Abias + (size_t)zb * sAbz + kcol);
                    v.x += bb.x; v.y += bb.y; v.z += bb.z; v.w += bb.w;
                }
                if (ASCALE) {
                    const float inv = 1.0f / S_;
                    v.x *= inv; v.y *= inv; v.z *= inv; v.w *= inv;
                }
            }
            ra[j] = v;
        }
        #pragma unroll
        for (int j = 0; j < 4; ++j) {
            int rB = n0 + j * 32 + rr;
            rb[j] = (rB < N) ? *(const float4*)(Bm + (size_t)rB * ldb + kcol)
                             : make_float4(0.f, 0.f, 0.f, 0.f);
        }
    };
    auto sts = [&](int s) {
        __nv_bfloat16* base = sm + s * STAGE;
        unsigned h0, h1, l0, l1;
        #pragma unroll
        for (int j = 0; j < BM / 32; ++j) {
            int row = j * 32 + rr;
            int off = row * 32 + ((((cc >> 1) ^ ((row >> 1) & 3)) << 3)) + ((cc & 1) << 2);
            split2(ra[j].x, ra[j].y, h0, l0);
            split2(ra[j].z, ra[j].w, h1, l1);
            *(uint2*)(base + off) = make_uint2(h0, h1);
            if (NSPLIT == 3) *(uint2*)(base + LO_OFF + off) = make_uint2(l0, l1);
        }
        #pragma unroll
        for (int j = 0; j < 4; ++j) {
            int row = j * 32 + rr;
            int off = APLANE + row * 32 + ((((cc >> 1) ^ ((row >> 1) & 3)) << 3)) + ((cc & 1) << 2);
            split2(rb[j].x, rb[j].y, h0, l0);
            split2(rb[j].z, rb[j].w, h1, l1);
            *(uint2*)(base + off) = make_uint2(h0, h1);
            if (NSPLIT == 3) *(uint2*)(base + LO_OFF + off) = make_uint2(l0, l1);
        }
    };
    auto compute = [&](int s) {
        unsigned aB = sbase + (unsigned)(s * STAGE) * 2u;
        unsigned bB = aB + (unsigned)APLANE * 2u;
        #pragma unroll
        for (int kk = 0; kk < 32; kk += 16) {
            unsigned ah[2][4], al[2][4];
            #pragma unroll
            for (int mi = 0; mi < 2; ++mi) {
                int row = warpM + mi * 16 + (lane & 15);
                int ch = (kk >> 3) + (lane >> 4);
                unsigned addr = aB +
                    (unsigned)(row * 32 + ((ch ^ ((row >> 1) & 3)) << 3)) * 2u;
                LDSM4(ah[mi], addr);
                if (NSPLIT == 3) LDSM4(al[mi], addr + (unsigned)LO_OFF * 2u);
            }
            unsigned bh[N8 / 2][4], bl[N8 / 2][4];
            #pragma unroll
            for (int ni = 0; ni < N8 / 2; ++ni) {
                int g = lane >> 3;
                int row = warpN + ni * 16 + ((g >> 1) << 3) + (lane & 7);
                int ch = (kk >> 3) + (g & 1);
                unsigned addr = bB +
                    (unsigned)(row * 32 + ((ch ^ ((row >> 1) & 3)) << 3)) * 2u;
                LDSM4(bh[ni], addr);
                if (NSPLIT == 3) LDSM4(bl[ni], addr + (unsigned)LO_OFF * 2u);
            }
            #pragma unroll
            for (int mi = 0; mi < 2; ++mi)
                #pragma unroll
                for (int n8 = 0; n8 < N8; ++n8) {
                    unsigned* hb = &bh[n8 >> 1][(n8 & 1) * 2];
                    MMA16816(acc[mi][n8], ah[mi], hb[0], hb[1]);
                    if (NSPLIT == 3) {
                        unsigned* lb = &bl[n8 >> 1][(n8 & 1) * 2];
                        MMA16816(acc[mi][n8], ah[mi], lb[0], lb[1]);
                        MMA16816(acc[mi][n8], al[mi], hb[0], hb[1]);
                    }
                }
        }
    };

    const int KT = Kc / 32;
    ldg(0);
    sts(0);
    __syncthreads();
    for (int t = 0; t < KT; ++t) {
        if (t + 1 < KT) ldg(t + 1);
        compute(t & 1);
        __syncthreads();
        if (t + 1 < KT) { sts((t + 1) & 1); __syncthreads(); }
    }

    #pragma unroll
    for (int mi = 0; mi < 2; ++mi) {
        int row = m0 + warpM + mi * 16 + (lane >> 2);
        #pragma unroll
        for (int n8 = 0; n8 < N8; ++n8) {
            int col = n0 + warpN + n8 * 8 + (lane & 3) * 2;
            if (row < M)
                *(float2*)(C + (size_t)row * ldc + col) =
                    make_float2(acc[mi][n8][0], acc[mi][n8][1]);
            if (row + 8 < M)
                *(float2*)(C + (size_t)(row + 8) * ldc + col) =
                    make_float2(acc[mi][n8][2], acc[mi][n8][3]);
        }
    }
}

// ---------------- split-K reduce (+bias, +gelu, +bf16 mirror) ----------------
template<int EPI, bool WBF>
__global__ void reduce_kernel(const float* __restrict__ part, float* __restrict__ C,
                              int ldc, const float* __restrict__ bias,
                              __nv_bfloat16* __restrict__ Cbf,
                              int MN, int N, int SPLIT)
{
    int i = blockIdx.x * 256 + threadIdx.x;
    if (i >= MN) return;
    const float* p = part + i;
    float s = 0.f;
    for (int k = 0; k < SPLIT; ++k) s += p[(size_t)k * MN];
    int n = i % N;
    if (bias) s += bias[n];
    if (EPI == 1) s = gelu_exact(s);
    C[(size_t)(i / N) * ldc + n] = s;
    if (WBF) Cbf[i] = __float2bfloat16(s);
}

// ---------------- scores: bf16 TC TN GEMM, 3-stage cp.async, bf16 out ---------
__device__ __forceinline__ unsigned bswz(int row, int chunk) {
    return (unsigned)(row * 64 + ((chunk ^ (row & 7)) * 8));
}
__global__ __launch_bounds__(256) void bgemm_kernel(
    const __nv_bfloat16* __restrict__ A, int lda,
    const __nv_bfloat16* __restrict__ B, int ldb,
    __nv_bfloat16* __restrict__ C, int ldc, int M, int N, int K)
{
    extern __shared__ __nv_bfloat16 sm[];
    const int tid = threadIdx.x, lane = tid & 31, warp = tid >> 5;
    const int warpM = (warp >> 1) * 32, warpN = (warp & 1) * 64;
    const int m0 = blockIdx.x * 128, n0 = blockIdx.y * 128;   // m fastest: B-tile L2 reuse
    unsigned sbase = (unsigned)__cvta_generic_to_shared(sm);

    float acc[2][8][4];
    #pragma unroll
    for (int a = 0; a < 2; ++a)
        #pragma unroll
        for (int b = 0; b < 8; ++b)
            #pragma unroll
            for (int c = 0; c < 4; ++c) acc[a][b][c] = 0.f;

    const int cidx = tid & 7, rbase = tid >> 3;
    auto load_stage = [&](int s, int k0) {
        unsigned aB = sbase + (unsigned)s * 32768u;
        unsigned bB = aB + 16384u;
        #pragma unroll
        for (int j = 0; j < 4; ++j) {
            int r = j * 32 + rbase;
            const __nv_bfloat16* srcA = A + (size_t)(m0 + r) * lda + k0 + cidx * 8;
            int szA = (m0 + r < M) ? 16 : 0;
            asm volatile("cp.async.cg.shared.global [%0], [%1], 16, %2;\n"
                         :: "r"(aB + bswz(r, cidx) * 2u), "l"(srcA), "r"(szA));
            const __nv_bfloat16* srcB = B + (size_t)(n0 + r) * ldb + k0 + cidx * 8;
            asm volatile("cp.async.cg.shared.global [%0], [%1], 16, 16;\n"
                         :: "r"(bB + bswz(r, cidx) * 2u), "l"(srcB));
        }
        asm volatile("cp.async.commit_group;\n" ::);
    };
    auto compute = [&](int s) {
        unsigned aB = sbase + (unsigned)s * 32768u;
        unsigned bB = aB + 16384u;
        #pragma unroll
        for (int kk = 0; kk < 64; kk += 16) {
            unsigned af[2][4];
            #pragma unroll
            for (int mi = 0; mi < 2; ++mi) {
                int row = warpM + mi * 16 + (lane & 15);
                int ch = (kk >> 3) + (lane >> 4);
                LDSM4(af[mi], aB + bswz(row, ch) * 2u);
            }
            unsigned bf[4][4];
            #pragma unroll
            for (int ni = 0; ni < 4; ++ni) {
                int g = lane >> 3;
                int row = warpN + ni * 16 + ((g >> 1) << 3) + (lane & 7);
                int ch = (kk >> 3) + (g & 1);
                LDSM4(bf[ni], bB + bswz(row, ch) * 2u);
            }
            #pragma unroll
            for (int mi = 0; mi < 2; ++mi)
                #pragma unroll
                for (int n8 = 0; n8 < 8; ++n8) {
                    unsigned* bb = &bf[n8 >> 1][(n8 & 1) * 2];
                    MMA16816(acc[mi][n8], af[mi], bb[0], bb[1]);
                }
        }
    };

    const int KT = K >> 6;
    load_stage(0, 0);
    load_stage(1, 64);
    for (int t = 0; t < KT; ++t) {
        if (t + 2 < KT) {
            asm volatile("cp.async.wait_group 1;\n" ::);
            __syncthreads();
            load_stage((t + 2) % 3, (t + 2) << 6);
        } else {
            asm volatile("cp.async.wait_group 0;\n" ::);
            __syncthreads();
        }
        compute(t % 3);
    }

    #pragma unroll
    for (int mi = 0; mi < 2; ++mi) {
        int row = m0 + warpM + mi * 16 + (lane >> 2);
        #pragma unroll
        for (int n8 = 0; n8 < 8; ++n8) {
            int col = n0 + warpN + n8 * 8 + (lane & 3) * 2;
            if (row < M)
                *(__nv_bfloat162*)(C + (size_t)row * ldc + col) =
                    __floats2bfloat162_rn(acc[mi][n8][0], acc[mi][n8][1]);
            if (row + 8 < M)
                *(__nv_bfloat162*)(C + (size_t)(row + 8) * ldc + col) =
                    __floats2bfloat162_rn(acc[mi][n8][2], acc[mi][n8][3]);
        }
    }
}

// ---------------- topk: sync-free per-warp top-32 -> 8-way merge -> z ---------
__global__ __launch_bounds__(256) void topk_kernel(
    const __nv_bfloat16* __restrict__ scores, const __nv_bfloat16* __restrict__ memb,
    float* __restrict__ z)
{
    extern __shared__ float sv[];            // M_ floats
    __shared__ float wvv[8 * KSEL];
    __shared__ int   wii[8 * KSEL];
    __shared__ float pw[KSEL];
    __shared__ int   pidx[KSEL];

    const int row = blockIdx.x, tid = threadIdx.x;
    const int lane = tid & 31, warp = tid >> 5;
    const __nv_bfloat16* sr = scores + (size_t)row * M_;

    #pragma unroll
    for (int j = 0; j < M_ / (256 * 8); ++j) {
        int i8 = (tid + j * 256) * 8;
        uint4 q = __ldcs((const uint4*)(sr + i8));
        const __nv_bfloat162* h = (const __nv_bfloat162*)&q;
        #pragma unroll
        for (int e = 0; e < 4; ++e) {
            float2 f = __bfloat1622float2(h[e]);
            sv[i8 + e * 2]     = f.x;
            sv[i8 + e * 2 + 1] = f.y;
        }
    }
    __syncthreads();

    const int base = warp * (M_ / 8);
    float bv = -INFINITY; int bi = base + lane;
    #pragma unroll 4
    for (int j = 0; j < M_ / 256; ++j) {
        int idx = base + lane + j * 32;
        float v = sv[idx];
        if (v > bv) { bv = v; bi = idx; }
    }
    for (int sel = 0; sel < KSEL; ++sel) {
        float v = bv; int ix = bi;
        #pragma unroll
        for (int o = 16; o > 0; o >>= 1) {
            float v2 = __shfl_down_sync(0xffffffffu, v, o);
            int   i2 = __shfl_down_sync(0xffffffffu, ix, o);
            if (v2 > v || (v2 == v && i2 < ix)) { v = v2; ix = i2; }
        }
        v  = __shfl_sync(0xffffffffu, v, 0);
        ix = __shfl_sync(0xffffffffu, ix, 0);
        if (lane == 0) { wvv[warp * KSEL + sel] = v; wii[warp * KSEL + sel] = ix; }
        if (((ix - base) & 31) == lane) {
            sv[ix] = -INFINITY;
            bv = -INFINITY; bi = base + lane;
            #pragma unroll 4
            for (int j = 0; j < M_ / 256; ++j) {
                int idx = base + lane + j * 32;
                float vv = sv[idx];
                if (vv > bv) { bv = vv; bi = idx; }
            }
        }
    }
    __syncthreads();

    if (warp == 0) {
        bool act = lane < 8;
        int head = 0;
        float cv = act ? wvv[lane * KSEL] : -INFINITY;
        int   ci = act ? wii[lane * KSEL] : 0x7fffffff;
        for (int sel = 0; sel < KSEL; ++sel) {
            float v = cv; int ix = ci; int src = lane;
            #pragma unroll
            for (int o = 16; o > 0; o >>= 1) {
                float v2 = __shfl_down_sync(0xffffffffu, v, o);
                int   i2 = __shfl_down_sync(0xffffffffu, ix, o);
                int   s2 = __shfl_down_sync(0xffffffffu, src, o);
                if (v2 > v || (v2 == v && i2 < ix)) { v = v2; ix = i2; src = s2; }
            }
            v   = __shfl_sync(0xffffffffu, v, 0);
            ix  = __shfl_sync(0xffffffffu, ix, 0);
            src = __shfl_sync(0xffffffffu, src, 0);
            if (lane == 0) { pw[sel] = v; pidx[sel] = ix; }
            if (lane == src) {
                ++head;
                cv = (head < KSEL) ? wvv[lane * KSEL + head] : -INFINITY;
                ci = (head < KSEL) ? wii[lane * KSEL + head] : 0x7fffffff;
            }
        }
        if (lane == 0) {
            float mx = pw[0], ssum = 0.f;
            for (int k = 0; k < KSEL; ++k) {
                float e = expf((pw[k] - mx) * 0.0625f);
                pw[k] = e; ssum += e;
            }
            float inv = 1.f / ssum;
            for (int k = 0; k < KSEL; ++k) pw[k] *= inv;
        }
    }
    __syncthreads();

    {
        int d0 = tid * 8;
        float av[8];
        #pragma unroll
        for (int e = 0; e < 8; ++e) av[e] = 0.f;
        #pragma unroll 4
        for (int k = 0; k < KSEL; ++k) {
            float p = pw[k];
            uint4 q = *(const uint4*)(memb + (size_t)pidx[k] * D_ + d0);
            const __nv_bfloat162* h = (const __nv_bfloat162*)&q;
            #pragma unroll
            for (int e = 0; e < 4; ++e) {
                float2 f = __bfloat1622float2(h[e]);
                av[e * 2]     += p * f.x;
                av[e * 2 + 1] += p * f.y;
            }
        }
        float* dst = z + (size_t)row * D_ + d0;
        *(float4*)(dst)     = make_float4(av[0], av[1], av[2], av[3]);
        *(float4*)(dst + 4) = make_float4(av[4], av[5], av[6], av[7]);
    }
}

// ---------------- head: exact fp32 warp-per-output dot ------------------------
__global__ void head_kernel(const float* __restrict__ fus, const float* __restrict__ hw,
                            const float* __restrict__ hb, float* __restrict__ out)
{
    int gw = (blockIdx.x * blockDim.x + threadIdx.x) >> 5;
    int lane = threadIdx.x & 31;
    if (gw >= B_ * C_) return;
    int b = gw / C_, c = gw % C_;
    const float4* fr = (const float4*)(fus + (size_t)b * D_);
    const float4* wr = (const float4*)(hw + (size_t)c * D_);
    float s = 0.f;
    #pragma unroll 4
    for (int j = lane; j < D_ / 4; j += 32) {
        float4 f = fr[j], w = wr[j];
        s += f.x * w.x + f.y * w.y + f.z * w.z + f.w * w.w;
    }
    #pragma unroll
    for (int o = 16; o > 0; o >>= 1) s += __shfl_down_sync(0xffffffffu, s, o);
    if (lane == 0) out[b * C_ + c] = s + hb[c];
}

// ---------------- launch --------------------------------------------------------
extern "C" void kernel_launch(void* const* d_in, const int* in_sizes, int n_in,
                              void* d_out, int out_size)
{
    const float* x      = (const float*)d_in[0];
    const float* mem    = (const float*)d_in[2];
    const float* ff_w   = (const float*)d_in[3];
    const float* ff_b   = (const float*)d_in[4];
    const float* mp_w   = (const float*)d_in[5];
    const float* mp_b   = (const float*)d_in[6];
    const float* wq     = (const float*)d_in[7];
    const float* bq     = (const float*)d_in[8];
    const float* wk     = (const float*)d_in[9];
    const float* wv     = (const float*)d_in[11];
    const float* bv     = (const float*)d_in[12];
    const float* wo     = (const float*)d_in[13];
    const float* bo     = (const float*)d_in[14];
    const float* fuse_w = (const float*)d_in[15];
    const float* fuse_b = (const float*)d_in[16];
    const float* head_w = (const float*)d_in[17];
    const float* head_b = (const float*)d_in[18];
    float* out = (float*)d_out;

    float *t, *u, *z, *fin, *fus, *part, *wkT, *mpwT;
    __nv_bfloat16 *u_bf, *mem_bf, *sc_bf;
    cudaGetSymbolAddress((void**)&t,    g_t);
    cudaGetSymbolAddress((void**)&u,    g_u);
    cudaGetSymbolAddress((void**)&z,    g_z);
    cudaGetSymbolAddress((void**)&fin,  g_fin);
    cudaGetSymbolAddress((void**)&fus,  g_fus);
    cudaGetSymbolAddress((void**)&part, g_part);
    cudaGetSymbolAddress((void**)&wkT,  g_wkT);
    cudaGetSymbolAddress((void**)&mpwT, g_mpwT);
    cudaGetSymbolAddress((void**)&u_bf,   g_u_bf);
    cudaGetSymbolAddress((void**)&mem_bf, g_mem_bf);
    cudaGetSymbolAddress((void**)&sc_bf,  g_sc_bf);

    cudaFuncSetAttribute((const void*)bgemm3_kernel<3,8,64,7,1>,  cudaFuncAttributeMaxDynamicSharedMemorySize, 49152);
    cudaFuncSetAttribute((const void*)bgemm3_kernel<3,8,64,8,0>,  cudaFuncAttributeMaxDynamicSharedMemorySize, 49152);
    cudaFuncSetAttribute((const void*)bgemm3_kernel<3,1,64,8,0>,  cudaFuncAttributeMaxDynamicSharedMemorySize, 49152);
    cudaFuncSetAttribute((const void*)bgemm3_kernel<3,2,128,1,0>, cudaFuncAttributeMaxDynamicSharedMemorySize, 65536);
    cudaFuncSetAttribute((const void*)bgemm3_kernel<1,2,128,1,0>, cudaFuncAttributeMaxDynamicSharedMemorySize, 32768);
    cudaFuncSetAttribute((const void*)bgemm3_kernel<1,4,64,2,0>,  cudaFuncAttributeMaxDynamicSharedMemorySize, 24576);
    cudaFuncSetAttribute((const void*)bgemm3_kernel<1,8,64,4,0>,  cudaFuncAttributeMaxDynamicSharedMemorySize, 24576);
    cudaFuncSetAttribute((const void*)bgemm3_kernel<3,8,64,1,0>,  cudaFuncAttributeMaxDynamicSharedMemorySize, 49152);
    cudaFuncSetAttribute((const void*)bgemm_kernel, cudaFuncAttributeMaxDynamicSharedMemorySize, 98304);
    cudaFuncSetAttribute((const void*)topk_kernel, cudaFuncAttributeMaxDynamicSharedMemorySize, M_ * 4);

    const long long BD  = (long long)B_ * D_;
    const long long BHD = (long long)B_ * H_ * D_;

    // ---- fork a side branch for prep (transposes + f2b) ----
    cudaStream_t s2;
    cudaStreamCreateWithFlags(&s2, cudaStreamNonBlocking);
    cudaEvent_t evFork, evT, evF;
    cudaEventCreateWithFlags(&evFork, cudaEventDisableTiming);
    cudaEventCreateWithFlags(&evT,    cudaEventDisableTiming);
    cudaEventCreateWithFlags(&evF,    cudaEventDisableTiming);

    cudaEventRecord(evFork, 0);
    cudaStreamWaitEvent(s2, evFork, 0);
    transpose_kernel<<<dim3(64, 64), dim3(32, 8), 0, s2>>>(wk, wkT);
    transpose_kernel<<<dim3(64, 64), dim3(32, 8), 0, s2>>>(mp_w, mpwT);
    cudaEventRecord(evT, s2);
    f2b_kernel<<<8192, 256, 0, s2>>>(mem, mem_bf, M_ * D_);
    cudaEventRecord(evF, s2);

    // ---- main branch ----
    // 1) mean partials -> PART2 (7 planes of B_*D_)
    mean1_kernel<<<dim3(2, B_, 7), 256>>>(x, part + PART2);

    // 2) xf partials: mean(x) @ ff_w^T -> part0 (8 planes); mean fused via SPLITA=7+scale
    bgemm3_kernel<3,8,64,7,1><<<dim3(16, 1, 8), 256, 49152>>>(
        part + PART2, D_, 0, BD, nullptr, 0, ff_w, D_, 0,
        part + PART0, D_, 0, BD, B_, D_, D_);

    // 3) q partials: (Σ xf_part + ff_b) @ wq^T -> part1 (8 planes)
    bgemm3_kernel<3,8,64,8,0><<<dim3(16, 1, 8), 256, 49152>>>(
        part + PART0, D_, 0, BD, ff_b, 0, wq, D_, 0,
        part + PART1, D_, 0, BD, B_, D_, D_);

    // 4) fin[:, :D] = xf (reduce part0 + ff_b)
    reduce_kernel<0,false><<<dim3(512, 1), 256>>>(
        part + PART0, fin, 2 * D_, ff_b, nullptr, B_ * D_, D_, 8);

    // join A: wkT + mpwT ready
    cudaStreamWaitEvent(0, evT, 0);

    // 5) t = (Σ q_part + bq)_h @ wk_h (TN via wkT; head offset = 256 COLUMNS)
    bgemm3_kernel<3,1,64,8,0><<<dim3(16, 1, H_), 256, 49152>>>(
        part + PART1, D_, DK_, BD, bq, DK_, wkT, D_, (long long)DK_,
        t, H_ * D_, D_, 0, B_, D_, DK_);

    // 6) u partials: t @ mp_w (TN via mpwT), split-K 2 -> part0; reduce emits u_bf
    bgemm3_kernel<3,2,128,1,0><<<dim3(16, 4, 2), 256, 65536>>>(
        t, D_, 0, 0, nullptr, 0, mpwT, D_, 0,
        part + PART0, D_, 0, BHD, B_ * H_, D_, D_);
    reduce_kernel<0,true><<<dim3(4096, 1), 256>>>(
        part + PART0, u, D_, nullptr, u_bf, B_ * H_ * D_, D_, 2);

    // join B: mem_bf ready
    cudaStreamWaitEvent(0, evF, 0);

    // 7) scores = u @ mem^T (bf16 TC, 3-stage; m fastest -> mem L2 reuse; bf16 out)
    bgemm_kernel<<<dim3(4, M_ / 128), 256, 98304>>>(
        u_bf, D_, mem_bf, D_, sc_bf, M_, B_ * H_, M_, D_);

    // 8) topk (bf16 scores) -> z (gather from bf16 mem)
    topk_kernel<<<B_ * H_, 256, M_ * 4>>>(sc_bf, mem_bf, z);

    // 9) y partials: z @ mp_w^T, split-K 2 -> part0
    bgemm3_kernel<1,2,128,1,0><<<dim3(16, 4, 2), 256, 32768>>>(
        z, D_, 0, 0, nullptr, 0, mp_w, D_, 0,
        part + PART0, D_, 0, BHD, B_ * H_, D_, D_);

    // 10) attn partials: (Σ y_part + mp_b)_h @ wv_h^T, split-K 4 -> part2
    bgemm3_kernel<1,4,64,2,0><<<dim3(2, 1, H_ * 4), 256, 24576>>>(
        part + PART0, H_ * D_, D_, BHD, mp_b, 0, wv, D_, (long long)DK_ * D_,
        part + PART2, D_, DK_, BD, B_, DK_, D_);

    // 11) resp partials: (Σ attn_part + bv) @ wo^T, split-K 8 -> part0
    bgemm3_kernel<1,8,64,4,0><<<dim3(16, 1, 8), 256, 24576>>>(
        part + PART2, D_, 0, BD, bv, 0, wo, D_, 0,
        part + PART0, D_, 0, BD, B_, D_, D_);

    // 12) fin[:, D:] = resp (reduce part0 + bo)
    reduce_kernel<0,false><<<dim3(512, 1), 256>>>(
        part + PART0, fin + D_, 2 * D_, bo, nullptr, B_ * D_, D_, 8);

    // 13) fus = gelu((fin @ fuse_w^T) + fuse_b), split-K 8 -> part1
    bgemm3_kernel<3,8,64,1,0><<<dim3(16, 1, 8), 256, 49152>>>(
        fin, 2 * D_, 0, 0, nullptr, 0, fuse_w, 2 * D_, 0,
        part + PART1, D_, 0, BD, B_, D_, 2 * D_);
    reduce_kernel<1,false><<<dim3(512, 1), 256>>>(
        part + PART1, fus, D_, fuse_b, nullptr, B_ * D_, D_, 8);

    // 14) logits (exact fp32)
    head_kernel<<<(B_ * C_ * 32 + 255) / 256, 256>>>(fus, head_w, head_b, out);
}

// round 13
// speedup vs baseline: 1.5293x; 1.0243x over previous
#include <cuda_runtime.h>
#include <cuda_bf16.h>
#include <math.h>

#define B_  64
#define S_  196
#define D_  2048
#define H_  8
#define DK_ 256
#define M_  16384
#define KSEL 32
#define C_  29

__device__ float g_t  [B_ * H_ * D_];
__device__ float g_u  [B_ * H_ * D_];
__device__ float g_z  [B_ * H_ * D_];
__device__ float g_fin[B_ * 2 * D_];
__device__ float g_fus[B_ * D_];
__device__ float g_part[4 * 512 * 2048];   // 16 MB scratch, region-multiplexed
__device__ float g_wkT [D_ * D_];
__device__ float g_mpwT[D_ * D_];
__device__ __nv_bfloat16 g_u_bf [B_ * H_ * D_];
__device__ __nv_bfloat16 g_mem_bf[M_ * D_];
__device__ __nv_bfloat16 g_sc_bf[B_ * H_ * M_];   // 16 MB

#define PART0 0
#define PART1 (1024 * 1024)
#define PART2 (2 * 1024 * 1024)

__device__ __forceinline__ float gelu_exact(float v) {
    return 0.5f * v * (1.0f + erff(v * 0.70710678118654752f));
}
__device__ __forceinline__ void split2(float a, float b, unsigned& hi, unsigned& lo) {
    __nv_bfloat162 h = __floats2bfloat162_rn(a, b);
    __nv_bfloat162 l = __floats2bfloat162_rn(a - __bfloat162float(h.x),
                                             b - __bfloat162float(h.y));
    hi = *(unsigned*)&h; lo = *(unsigned*)&l;
}

#define LDSM4(R, ADDR) asm volatile( \
    "ldmatrix.sync.aligned.m8n8.x4.shared.b16 {%0,%1,%2,%3}, [%4];" \
    : "=r"((R)[0]), "=r"((R)[1]), "=r"((R)[2]), "=r"((R)[3]) : "r"(ADDR))
#define MMA16816(D, A, B0, B1) asm volatile( \
    "mma.sync.aligned.m16n8k16.row.col.f32.bf16.bf16.f32 " \
    "{%0,%1,%2,%3},{%4,%5,%6,%7},{%8,%9},{%0,%1,%2,%3};" \
    : "+f"((D)[0]), "+f"((D)[1]), "+f"((D)[2]), "+f"((D)[3]) \
    : "r"((A)[0]), "r"((A)[1]), "r"((A)[2]), "r"((A)[3]), "r"(B0), "r"(B1))

// ---------------- transpose fp32 DxD ----------------
__global__ void transpose_kernel(const float* __restrict__ in, float* __restrict__ out) {
    __shared__ float tile[32][33];
    int x = blockIdx.x * 32 + threadIdx.x;
    #pragma unroll
    for (int j = threadIdx.y; j < 32; j += 8)
        tile[j][threadIdx.x] = __ldcs(&in[(size_t)(blockIdx.y * 32 + j) * D_ + x]);
    __syncthreads();
    int xo = blockIdx.y * 32 + threadIdx.x;
    #pragma unroll
    for (int j = threadIdx.y; j < 32; j += 8)
        out[(size_t)(blockIdx.x * 32 + j) * D_ + xo] = tile[threadIdx.x][j];
}

// ---------------- fp32 -> bf16, streaming ----------------
__global__ void f2b_kernel(const float* __restrict__ a, __nv_bfloat16* __restrict__ o, int n) {
    int stride = gridDim.x * blockDim.x * 16;
    for (int i = (blockIdx.x * blockDim.x + threadIdx.x) * 16; i < n; i += stride) {
        float4 v0 = __ldcs((const float4*)(a + i));
        float4 v1 = __ldcs((const float4*)(a + i + 4));
        float4 v2 = __ldcs((const float4*)(a + i + 8));
        float4 v3 = __ldcs((const float4*)(a + i + 12));
        __nv_bfloat162 r[8];
        r[0] = __floats2bfloat162_rn(v0.x, v0.y);
        r[1] = __floats2bfloat162_rn(v0.z, v0.w);
        r[2] = __floats2bfloat162_rn(v1.x, v1.y);
        r[3] = __floats2bfloat162_rn(v1.z, v1.w);
        r[4] = __floats2bfloat162_rn(v2.x, v2.y);
        r[5] = __floats2bfloat162_rn(v2.z, v2.w);
        r[6] = __floats2bfloat162_rn(v3.x, v3.y);
        r[7] = __floats2bfloat162_rn(v3.z, v3.w);
        __stcs((uint4*)(o + i),     *(uint4*)&r[0]);
        __stcs((uint4*)(o + i + 8), *(uint4*)&r[4]);
    }
}

// ---------------- mean over S: phase 1 (7 chunks of 28) ----------------
#define SCHUNK 28
__global__ void mean1_kernel(const float* __restrict__ x, float* __restrict__ part) {
    int d4 = blockIdx.x * 256 + threadIdx.x;
    int b = blockIdx.y;
    int sc = blockIdx.z;
    const float4* xp = (const float4*)(x + (size_t)b * S_ * D_) + (size_t)(sc * SCHUNK) * (D_ / 4) + d4;
    float4 s = make_float4(0.f, 0.f, 0.f, 0.f);
    #pragma unroll 7
    for (int i = 0; i < SCHUNK; ++i) {
        float4 v = __ldcs(xp + (size_t)i * (D_ / 4));
        s.x += v.x; s.y += v.y; s.z += v.z; s.w += v.w;
    }
    ((float4*)(part + ((size_t)sc * B_ + b) * D_))[d4] = s;
}

// ---------------- unified TC TN GEMM, fp32 in/out, in-reg bf16 ----------------
template<int NSPLIT, int SPLITK, int BM, int SPLITA, int ASCALE>
__global__ __launch_bounds__(256) void bgemm3_kernel(
    const float* __restrict__ A, int lda, long long sAz, long long sAs,
    const float* __restrict__ Abias, int sAbz,
    const float* __restrict__ Bm, int ldb, long long sBz,
    float* __restrict__ C, int ldc, long long sCz, long long sCs,
    int M, int N, int K)
{
    extern __shared__ __nv_bfloat16 sm[];
    constexpr int APLANE = BM * 32;
    constexpr int LO_OFF = APLANE + 4096;
    constexpr int STAGE  = LO_OFF * ((NSPLIT == 3) ? 2 : 1);
    constexpr int N8     = (BM == 128) ? 8 : 4;
    const int tid = threadIdx.x, lane = tid & 31, warp = tid >> 5;
    const int warpM = (BM == 128) ? (warp >> 1) * 32 : (warp >> 2) * 32;
    const int warpN = (BM == 128) ? (warp & 1) * 64 : (warp & 3) * 32;
    const int m0 = blockIdx.y * BM;
    const int n0 = blockIdx.x * 128;
    const int zb = blockIdx.z / SPLITK, sk = blockIdx.z % SPLITK;
    const int Kc = K / SPLITK, k0base = sk * Kc;

    A  += (size_t)zb * sAz;
    Bm += (size_t)zb * sBz;
    C  += (size_t)zb * sCz + (size_t)sk * sCs;

    const int cc = tid & 7, rr = tid >> 3;
    float4 ra[BM / 32], rb[4];
    unsigned sbase = (unsigned)__cvta_generic_to_shared(sm);

    float acc[2][N8][4];
    #pragma unroll
    for (int a = 0; a < 2; ++a)
        #pragma unroll
        for (int b = 0; b < N8; ++b)
            #pragma unroll
            for (int c = 0; c < 4; ++c) acc[a][b][c] = 0.f;

    auto ldg = [&](int kt) {
        int kcol = k0base + kt * 32 + cc * 4;
        #pragma unroll
        for (int j = 0; j < BM / 32; ++j) {
            int rA = m0 + j * 32 + rr;
            float4 v = make_float4(0.f, 0.f, 0.f, 0.f);
            if (rA < M) {
                v = *(const float4*)(A + (size_t)rA * lda + kcol);
                #pragma unroll
                for (int s = 1; s < SPLITA; ++s) {
                    float4 w = *(const float4*)(A + (size_t)s * sAs + (size_t)rA * lda + kcol);
                    v.x += w.x; v.y += w.y; v.z += w.z; v.w += w.w;
                }
                if (Abias) {
                    float4 bb = *(const float4*)(Abias + (size_t)zb * sAbz + kcol);
                    v.x += bb.x; v.y += bb.y; v.z += bb.z; v.w += bb.w;
                }
                if (ASCALE) {
                    const float inv = 1.0f / S_;
                    v.x *= inv; v.y *= inv; v.z *= inv; v.w *= inv;
                }
            }
            ra[j] = v;
        }
        #pragma unroll
        for (int j = 0; j < 4; ++j) {
            int rB = n0 + j * 32 + rr;
            rb[j] = (rB < N) ? *(const float4*)(Bm + (size_t)rB * ldb + kcol)
                             : make_float4(0.f, 0.f, 0.f, 0.f);
        }
    };
    auto sts = [&](int s) {
        __nv_bfloat16* base = sm + s * STAGE;
        unsigned h0, h1, l0, l1;
        #pragma unroll
        for (int j = 0; j < BM / 32; ++j) {
            int row = j * 32 + rr;
            int off = row * 32 + ((((cc >> 1) ^ ((row >> 1) & 3)) << 3)) + ((cc & 1) << 2);
            split2(ra[j].x, ra[j].y, h0, l0);
            split2(ra[j].z, ra[j].w, h1, l1);
            *(uint2*)(base + off) = make_uint2(h0, h1);
            if (NSPLIT == 3) *(uint2*)(base + LO_OFF + off) = make_uint2(l0, l1);
        }
        #pragma unroll
        for (int j = 0; j < 4; ++j) {
            int row = j * 32 + rr;
            int off = APLANE + row * 32 + ((((cc >> 1) ^ ((row >> 1) & 3)) << 3)) + ((cc & 1) << 2);
            split2(rb[j].x, rb[j].y, h0, l0);
            split2(rb[j].z, rb[j].w, h1, l1);
            *(uint2*)(base + off) = make_uint2(h0, h1);
            if (NSPLIT == 3) *(uint2*)(base + LO_OFF + off) = make_uint2(l0, l1);
        }
    };
    auto compute = [&](int s) {
        unsigned aB = sbase + (unsigned)(s * STAGE) * 2u;
        unsigned bB = aB + (unsigned)APLANE * 2u;
        #pragma unroll
        for (int kk = 0; kk < 32; kk += 16) {
            unsigned ah[2][4], al[2][4];
            #pragma unroll
            for (int mi = 0; mi < 2; ++mi) {
                int row = warpM + mi * 16 + (lane & 15);
                int ch = (kk >> 3) + (lane >> 4);
                unsigned addr = aB +
                    (unsigned)(row * 32 + ((ch ^ ((row >> 1) & 3)) << 3)) * 2u;
                LDSM4(ah[mi], addr);
                if (NSPLIT == 3) LDSM4(al[mi], addr + (unsigned)LO_OFF * 2u);
            }
            unsigned bh[N8 / 2][4], bl[N8 / 2][4];
            #pragma unroll
            for (int ni = 0; ni < N8 / 2; ++ni) {
                int g = lane >> 3;
                int row = warpN + ni * 16 + ((g >> 1) << 3) + (lane & 7);
                int ch = (kk >> 3) + (g & 1);
                unsigned addr = bB +
                    (unsigned)(row * 32 + ((ch ^ ((row >> 1) & 3)) << 3)) * 2u;
                LDSM4(bh[ni], addr);
                if (NSPLIT == 3) LDSM4(bl[ni], addr + (unsigned)LO_OFF * 2u);
            }
            #pragma unroll
            for (int mi = 0; mi < 2; ++mi)
                #pragma unroll
                for (int n8 = 0; n8 < N8; ++n8) {
                    unsigned* hb = &bh[n8 >> 1][(n8 & 1) * 2];
                    MMA16816(acc[mi][n8], ah[mi], hb[0], hb[1]);
                    if (NSPLIT == 3) {
                        unsigned* lb = &bl[n8 >> 1][(n8 & 1) * 2];
                        MMA16816(acc[mi][n8], ah[mi], lb[0], lb[1]);
                        MMA16816(acc[mi][n8], al[mi], hb[0], hb[1]);
                    }
                }
        }
    };

    const int KT = Kc / 32;
    ldg(0);
    sts(0);
    __syncthreads();
    for (int t = 0; t < KT; ++t) {
        if (t + 1 < KT) ldg(t + 1);
        compute(t & 1);
        // NOTE: no barrier needed here — sts below writes buffer (t+1)&1,
        // which compute(t) does not read; its last reader, compute(t-1),
        // was fenced by the barrier at the end of iteration t-1.
        if (t + 1 < KT) { sts((t + 1) & 1); __syncthreads(); }
    }

    #pragma unroll
    for (int mi = 0; mi < 2; ++mi) {
        int row = m0 + warpM + mi * 16 + (lane >> 2);
        #pragma unroll
        for (int n8 = 0; n8 < N8; ++n8) {
            int col = n0 + warpN + n8 * 8 + (lane & 3) * 2;
            if (row < M)
                *(float2*)(C + (size_t)row * ldc + col) =
                    make_float2(acc[mi][n8][0], acc[mi][n8][1]);
            if (row + 8 < M)
                *(float2*)(C + (size_t)(row + 8) * ldc + col) =
                    make_float2(acc[mi][n8][2], acc[mi][n8][3]);
        }
    }
}

// ---------------- split-K reduce (+bias, +gelu, +bf16 mirror) ----------------
template<int EPI, bool WBF>
__global__ void reduce_kernel(const float* __restrict__ part, float* __restrict__ C,
                              int ldc, const float* __restrict__ bias,
                              __nv_bfloat16* __restrict__ Cbf,
                              int MN, int N, int SPLIT)
{
    int i = blockIdx.x * 256 + threadIdx.x;
    if (i >= MN) return;
    const float* p = part + i;
    float s = 0.f;
    for (int k = 0; k < SPLIT; ++k) s += p[(size_t)k * MN];
    int n = i % N;
    if (bias) s += bias[n];
    if (EPI == 1) s = gelu_exact(s);
    C[(size_t)(i / N) * ldc + n] = s;
    if (WBF) Cbf[i] = __float2bfloat16(s);
}

// ---------------- scores: bf16 TC TN GEMM, 3-stage cp.async, bf16 out ---------
__device__ __forceinline__ unsigned bswz(int row, int chunk) {
    return (unsigned)(row * 64 + ((chunk ^ (row & 7)) * 8));
}
__global__ __launch_bounds__(256) void bgemm_kernel(
    const __nv_bfloat16* __restrict__ A, int lda,
    const __nv_bfloat16* __restrict__ B, int ldb,
    __nv_bfloat16* __restrict__ C, int ldc, int M, int N, int K)
{
    extern __shared__ __nv_bfloat16 sm[];
    const int tid = threadIdx.x, lane = tid & 31, warp = tid >> 5;
    const int warpM = (warp >> 1) * 32, warpN = (warp & 1) * 64;
    const int m0 = blockIdx.x * 128, n0 = blockIdx.y * 128;   // m fastest: B-tile L2 reuse
    unsigned sbase = (unsigned)__cvta_generic_to_shared(sm);

    float acc[2][8][4];
    #pragma unroll
    for (int a = 0; a < 2; ++a)
        #pragma unroll
        for (int b = 0; b < 8; ++b)
            #pragma unroll
            for (int c = 0; c < 4; ++c) acc[a][b][c] = 0.f;

    const int cidx = tid & 7, rbase = tid >> 3;
    auto load_stage = [&](int s, int k0) {
        unsigned aB = sbase + (unsigned)s * 32768u;
        unsigned bB = aB + 16384u;
        #pragma unroll
        for (int j = 0; j < 4; ++j) {
            int r = j * 32 + rbase;
            const __nv_bfloat16* srcA = A + (size_t)(m0 + r) * lda + k0 + cidx * 8;
            int szA = (m0 + r < M) ? 16 : 0;
            asm volatile("cp.async.cg.shared.global [%0], [%1], 16, %2;\n"
                         :: "r"(aB + bswz(r, cidx) * 2u), "l"(srcA), "r"(szA));
            const __nv_bfloat16* srcB = B + (size_t)(n0 + r) * ldb + k0 + cidx * 8;
            asm volatile("cp.async.cg.shared.global [%0], [%1], 16, 16;\n"
                         :: "r"(bB + bswz(r, cidx) * 2u), "l"(srcB));
        }
        asm volatile("cp.async.commit_group;\n" ::);
    };
    auto compute = [&](int s) {
        unsigned aB = sbase + (unsigned)s * 32768u;
        unsigned bB = aB + 16384u;
        #pragma unroll
        for (int kk = 0; kk < 64; kk += 16) {
            unsigned af[2][4];
            #pragma unroll
            for (int mi = 0; mi < 2; ++mi) {
                int row = warpM + mi * 16 + (lane & 15);
                int ch = (kk >> 3) + (lane >> 4);
                LDSM4(af[mi], aB + bswz(row, ch) * 2u);
            }
            unsigned bf[4][4];
            #pragma unroll
            for (int ni = 0; ni < 4; ++ni) {
                int g = lane >> 3;
                int row = warpN + ni * 16 + ((g >> 1) << 3) + (lane & 7);
                int ch = (kk >> 3) + (g & 1);
                LDSM4(bf[ni], bB + bswz(row, ch) * 2u);
            }
            #pragma unroll
            for (int mi = 0; mi < 2; ++mi)
                #pragma unroll
                for (int n8 = 0; n8 < 8; ++n8) {
                    unsigned* bb = &bf[n8 >> 1][(n8 & 1) * 2];
                    MMA16816(acc[mi][n8], af[mi], bb[0], bb[1]);
                }
        }
    };

    const int KT = K >> 6;
    load_stage(0, 0);
    load_stage(1, 64);
    for (int t = 0; t < KT; ++t) {
        if (t + 2 < KT) {
            asm volatile("cp.async.wait_group 1;\n" ::);
            __syncthreads();
            load_stage((t + 2) % 3, (t + 2) << 6);
        } else {
            asm volatile("cp.async.wait_group 0;\n" ::);
            __syncthreads();
        }
        compute(t % 3);
    }

    #pragma unroll
    for (int mi = 0; mi < 2; ++mi) {
        int row = m0 + warpM + mi * 16 + (lane >> 2);
        #pragma unroll
        for (int n8 = 0; n8 < 8; ++n8) {
            int col = n0 + warpN + n8 * 8 + (lane & 3) * 2;
            if (row < M)
                *(__nv_bfloat162*)(C + (size_t)row * ldc + col) =
                    __floats2bfloat162_rn(acc[mi][n8][0], acc[mi][n8][1]);
            if (row + 8 < M)
                *(__nv_bfloat162*)(C + (size_t)(row + 8) * ldc + col) =
                    __floats2bfloat162_rn(acc[mi][n8][2], acc[mi][n8][3]);
        }
    }
}

// ---------------- topk: sync-free per-warp top-32 -> 8-way merge -> z ---------
__global__ __launch_bounds__(256) void topk_kernel(
    const __nv_bfloat16* __restrict__ scores, const __nv_bfloat16* __restrict__ memb,
    float* __restrict__ z)
{
    extern __shared__ float sv[];            // M_ floats
    __shared__ float wvv[8 * KSEL];
    __shared__ int   wii[8 * KSEL];
    __shared__ float pw[KSEL];
    __shared__ int   pidx[KSEL];

    const int row = blockIdx.x, tid = threadIdx.x;
    const int lane = tid & 31, warp = tid >> 5;
    const __nv_bfloat16* sr = scores + (size_t)row * M_;

    #pragma unroll
    for (int j = 0; j < M_ / (256 * 8); ++j) {
        int i8 = (tid + j * 256) * 8;
        uint4 q = __ldcs((const uint4*)(sr + i8));
        const __nv_bfloat162* h = (const __nv_bfloat162*)&q;
        #pragma unroll
        for (int e = 0; e < 4; ++e) {
            float2 f = __bfloat1622float2(h[e]);
            sv[i8 + e * 2]     = f.x;
            sv[i8 + e * 2 + 1] = f.y;
        }
    }
    __syncthreads();

    const int base = warp * (M_ / 8);
    float bv = -INFINITY; int bi = base + lane;
    #pragma unroll 4
    for (int j = 0; j < M_ / 256; ++j) {
        int idx = base + lane + j * 32;
        float v = sv[idx];
        if (v > bv) { bv = v; bi = idx; }
    }
    for (int sel = 0; sel < KSEL; ++sel) {
        float v = bv; int ix = bi;
        #pragma unroll
        for (int o = 16; o > 0; o >>= 1) {
            float v2 = __shfl_down_sync(0xffffffffu, v, o);
            int   i2 = __shfl_down_sync(0xffffffffu, ix, o);
            if (v2 > v || (v2 == v && i2 < ix)) { v = v2; ix = i2; }
        }
        v  = __shfl_sync(0xffffffffu, v, 0);
        ix = __shfl_sync(0xffffffffu, ix, 0);
        if (lane == 0) { wvv[warp * KSEL + sel] = v; wii[warp * KSEL + sel] = ix; }
        if (((ix - base) & 31) == lane) {
            sv[ix] = -INFINITY;
            bv = -INFINITY; bi = base + lane;
            #pragma unroll 4
            for (int j = 0; j < M_ / 256; ++j) {
                int idx = base + lane + j * 32;
                float vv = sv[idx];
                if (vv > bv) { bv = vv; bi = idx; }
            }
        }
    }
    __syncthreads();

    if (warp == 0) {
        bool act = lane < 8;
        int head = 0;
        float cv = act ? wvv[lane * KSEL] : -INFINITY;
        int   ci = act ? wii[lane * KSEL] : 0x7fffffff;
        for (int sel = 0; sel < KSEL; ++sel) {
            float v = cv; int ix = ci; int src = lane;
            #pragma unroll
            for (int o = 16; o > 0; o >>= 1) {
                float v2 = __shfl_down_sync(0xffffffffu, v, o);
                int   i2 = __shfl_down_sync(0xffffffffu, ix, o);
                int   s2 = __shfl_down_sync(0xffffffffu, src, o);
                if (v2 > v || (v2 == v && i2 < ix)) { v = v2; ix = i2; src = s2; }
            }
            v   = __shfl_sync(0xffffffffu, v, 0);
            ix  = __shfl_sync(0xffffffffu, ix, 0);
            src = __shfl_sync(0xffffffffu, src, 0);
            if (lane == 0) { pw[sel] = v; pidx[sel] = ix; }
            if (lane == src) {
                ++head;
                cv = (head < KSEL) ? wvv[lane * KSEL + head] : -INFINITY;
                ci = (head < KSEL) ? wii[lane * KSEL + head] : 0x7fffffff;
            }
        }
        if (lane == 0) {
            float mx = pw[0], ssum = 0.f;
            for (int k = 0; k < KSEL; ++k) {
                float e = expf((pw[k] - mx) * 0.0625f);
                pw[k] = e; ssum += e;
            }
            float inv = 1.f / ssum;
            for (int k = 0; k < KSEL; ++k) pw[k] *= inv;
        }
    }
    __syncthreads();

    {
        int d0 = tid * 8;
        float av[8];
        #pragma unroll
        for (int e = 0; e < 8; ++e) av[e] = 0.f;
        #pragma unroll 4
        for (int k = 0; k < KSEL; ++k) {
            float p = pw[k];
            uint4 q = *(const uint4*)(memb + (size_t)pidx[k] * D_ + d0);
            const __nv_bfloat162* h = (const __nv_bfloat162*)&q;
            #pragma unroll
            for (int e = 0; e < 4; ++e) {
                float2 f = __bfloat1622float2(h[e]);
                av[e * 2]     += p * f.x;
                av[e * 2 + 1] += p * f.y;
            }
        }
        float* dst = z + (size_t)row * D_ + d0;
        *(float4*)(dst)     = make_float4(av[0], av[1], av[2], av[3]);
        *(float4*)(dst + 4) = make_float4(av[4], av[5], av[6], av[7]);
    }
}

// ---------------- head: exact fp32 warp-per-output dot ------------------------
__global__ void head_kernel(const float* __restrict__ fus, const float* __restrict__ hw,
                            const float* __restrict__ hb, float* __restrict__ out)
{
    int gw = (blockIdx.x * blockDim.x + threadIdx.x) >> 5;
    int lane = threadIdx.x & 31;
    if (gw >= B_ * C_) return;
    int b = gw / C_, c = gw % C_;
    const float4* fr = (const float4*)(fus + (size_t)b * D_);
    const float4* wr = (const float4*)(hw + (size_t)c * D_);
    float s = 0.f;
    #pragma unroll 4
    for (int j = lane; j < D_ / 4; j += 32) {
        float4 f = fr[j], w = wr[j];
        s += f.x * w.x + f.y * w.y + f.z * w.z + f.w * w.w;
    }
    #pragma unroll
    for (int o = 16; o > 0; o >>= 1) s += __shfl_down_sync(0xffffffffu, s, o);
    if (lane == 0) out[b * C_ + c] = s + hb[c];
}

// ---------------- launch --------------------------------------------------------
extern "C" void kernel_launch(void* const* d_in, const int* in_sizes, int n_in,
                              void* d_out, int out_size)
{
    const float* x      = (const float*)d_in[0];
    const float* mem    = (const float*)d_in[2];
    const float* ff_w   = (const float*)d_in[3];
    const float* ff_b   = (const float*)d_in[4];
    const float* mp_w   = (const float*)d_in[5];
    const float* mp_b   = (const float*)d_in[6];
    const float* wq     = (const float*)d_in[7];
    const float* bq     = (const float*)d_in[8];
    const float* wk     = (const float*)d_in[9];
    const float* wv     = (const float*)d_in[11];
    const float* bv     = (const float*)d_in[12];
    const float* wo     = (const float*)d_in[13];
    const float* bo     = (const float*)d_in[14];
    const float* fuse_w = (const float*)d_in[15];
    const float* fuse_b = (const float*)d_in[16];
    const float* head_w = (const float*)d_in[17];
    const float* head_b = (const float*)d_in[18];
    float* out = (float*)d_out;

    float *t, *u, *z, *fin, *fus, *part, *wkT, *mpwT;
    __nv_bfloat16 *u_bf, *mem_bf, *sc_bf;
    cudaGetSymbolAddress((void**)&t,    g_t);
    cudaGetSymbolAddress((void**)&u,    g_u);
    cudaGetSymbolAddress((void**)&z,    g_z);
    cudaGetSymbolAddress((void**)&fin,  g_fin);
    cudaGetSymbolAddress((void**)&fus,  g_fus);
    cudaGetSymbolAddress((void**)&part, g_part);
    cudaGetSymbolAddress((void**)&wkT,  g_wkT);
    cudaGetSymbolAddress((void**)&mpwT, g_mpwT);
    cudaGetSymbolAddress((void**)&u_bf,   g_u_bf);
    cudaGetSymbolAddress((void**)&mem_bf, g_mem_bf);
    cudaGetSymbolAddress((void**)&sc_bf,  g_sc_bf);

    cudaFuncSetAttribute((const void*)bgemm3_kernel<3,8,64,7,1>,  cudaFuncAttributeMaxDynamicSharedMemorySize, 49152);
    cudaFuncSetAttribute((const void*)bgemm3_kernel<1,8,64,8,0>,  cudaFuncAttributeMaxDynamicSharedMemorySize, 24576);
    cudaFuncSetAttribute((const void*)bgemm3_kernel<1,1,64,8,0>,  cudaFuncAttributeMaxDynamicSharedMemorySize, 24576);
    cudaFuncSetAttribute((const void*)bgemm3_kernel<1,2,128,1,0>, cudaFuncAttributeMaxDynamicSharedMemorySize, 32768);
    cudaFuncSetAttribute((const void*)bgemm3_kernel<1,4,64,2,0>,  cudaFuncAttributeMaxDynamicSharedMemorySize, 24576);
    cudaFuncSetAttribute((const void*)bgemm3_kernel<1,8,64,4,0>,  cudaFuncAttributeMaxDynamicSharedMemorySize, 24576);
    cudaFuncSetAttribute((const void*)bgemm3_kernel<3,8,64,1,0>,  cudaFuncAttributeMaxDynamicSharedMemorySize, 49152);
    cudaFuncSetAttribute((const void*)bgemm_kernel, cudaFuncAttributeMaxDynamicSharedMemorySize, 98304);
    cudaFuncSetAttribute((const void*)topk_kernel, cudaFuncAttributeMaxDynamicSharedMemorySize, M_ * 4);

    const long long BD  = (long long)B_ * D_;
    const long long BHD = (long long)B_ * H_ * D_;

    // ---- fork a side branch for prep (transposes + f2b) ----
    cudaStream_t s2;
    cudaStreamCreateWithFlags(&s2, cudaStreamNonBlocking);
    cudaEvent_t evFork, evT, evF;
    cudaEventCreateWithFlags(&evFork, cudaEventDisableTiming);
    cudaEventCreateWithFlags(&evT,    cudaEventDisableTiming);
    cudaEventCreateWithFlags(&evF,    cudaEventDisableTiming);

    cudaEventRecord(evFork, 0);
    cudaStreamWaitEvent(s2, evFork, 0);
    transpose_kernel<<<dim3(64, 64), dim3(32, 8), 0, s2>>>(wk, wkT);
    transpose_kernel<<<dim3(64, 64), dim3(32, 8), 0, s2>>>(mp_w, mpwT);
    cudaEventRecord(evT, s2);
    f2b_kernel<<<8192, 256, 0, s2>>>(mem, mem_bf, M_ * D_);
    cudaEventRecord(evF, s2);

    // ---- main branch ----
    // 1) mean partials -> PART2 (7 planes of B_*D_)
    mean1_kernel<<<dim3(2, B_, 7), 256>>>(x, part + PART2);

    // 2) xf partials: mean(x) @ ff_w^T -> part0 (8 planes); NSPLIT=3 (output path)
    bgemm3_kernel<3,8,64,7,1><<<dim3(16, 1, 8), 256, 49152>>>(
        part + PART2, D_, 0, BD, nullptr, 0, ff_w, D_, 0,
        part + PART0, D_, 0, BD, B_, D_, D_);

    // 3) q partials: (Σ xf_part + ff_b) @ wq^T -> part1; NSPLIT=1 (selection-only)
    bgemm3_kernel<1,8,64,8,0><<<dim3(16, 1, 8), 256, 24576>>>(
        part + PART0, D_, 0, BD, ff_b, 0, wq, D_, 0,
        part + PART1, D_, 0, BD, B_, D_, D_);

    // 4) fin[:, :D] = xf (reduce part0 + ff_b)
    reduce_kernel<0,false><<<dim3(512, 1), 256>>>(
        part + PART0, fin, 2 * D_, ff_b, nullptr, B_ * D_, D_, 8);

    // join A: wkT + mpwT ready
    cudaStreamWaitEvent(0, evT, 0);

    // 5) t = (Σ q_part + bq)_h @ wk_h; NSPLIT=1
    bgemm3_kernel<1,1,64,8,0><<<dim3(16, 1, H_), 256, 24576>>>(
        part + PART1, D_, DK_, BD, bq, DK_, wkT, D_, (long long)DK_,
        t, H_ * D_, D_, 0, B_, D_, DK_);

    // 6) u partials: t @ mp_w (TN via mpwT), NSPLIT=1, split-K 2 -> part0
    bgemm3_kernel<1,2,128,1,0><<<dim3(16, 4, 2), 256, 32768>>>(
        t, D_, 0, 0, nullptr, 0, mpwT, D_, 0,
        part + PART0, D_, 0, BHD, B_ * H_, D_, D_);
    reduce_kernel<0,true><<<dim3(4096, 1), 256>>>(
        part + PART0, u, D_, nullptr, u_bf, B_ * H_ * D_, D_, 2);

    // join B: mem_bf ready
    cudaStreamWaitEvent(0, evF, 0);

    // 7) scores = u @ mem^T (bf16 TC, 3-stage; m fastest; bf16 out)
    bgemm_kernel<<<dim3(4, M_ / 128), 256, 98304>>>(
        u_bf, D_, mem_bf, D_, sc_bf, M_, B_ * H_, M_, D_);

    // 8) topk (bf16 scores) -> z (gather from bf16 mem)
    topk_kernel<<<B_ * H_, 256, M_ * 4>>>(sc_bf, mem_bf, z);

    // 9) y partials: z @ mp_w^T, split-K 2 -> part0
    bgemm3_kernel<1,2,128,1,0><<<dim3(16, 4, 2), 256, 32768>>>(
        z, D_, 0, 0, nullptr, 0, mp_w, D_, 0,
        part + PART0, D_, 0, BHD, B_ * H_, D_, D_);

    // 10) attn partials: (Σ y_part + mp_b)_h @ wv_h^T, split-K 4 -> part2
    bgemm3_kernel<1,4,64,2,0><<<dim3(2, 1, H_ * 4), 256, 24576>>>(
        part + PART0, H_ * D_, D_, BHD, mp_b, 0, wv, D_, (long long)DK_ * D_,
        part + PART2, D_, DK_, BD, B_, DK_, D_);

    // 11) resp partials: (Σ attn_part + bv) @ wo^T, split-K 8 -> part0
    bgemm3_kernel<1,8,64,4,0><<<dim3(16, 1, 8), 256, 24576>>>(
        part + PART2, D_, 0, BD, bv, 0, wo, D_, 0,
        part + PART0, D_, 0, BD, B_, D_, D_);

    // 12) fin[:, D:] = resp (reduce part0 + bo)
    reduce_kernel<0,false><<<dim3(512, 1), 256>>>(
        part + PART0, fin + D_, 2 * D_, bo, nullptr, B_ * D_, D_, 8);

    // 13) fus = gelu((fin @ fuse_w^T) + fuse_b), NSPLIT=3, split-K 8 -> part1
    bgemm3_kernel<3,8,64,1,0><<<dim3(16, 1, 8), 256, 49152>>>(
        fin, 2 * D_, 0, 0, nullptr, 0, fuse_w, 2 * D_, 0,
        part + PART1, D_, 0, BD, B_, D_, 2 * D_);
    reduce_kernel<1,false><<<dim3(512, 1), 256>>>(
        part + PART1, fus, D_, fuse_b, nullptr, B_ * D_, D_, 8);

    // 14) logits (exact fp32)
    head_kernel<<<(B_ * C_ * 32 + 255) / 256, 256>>>(fus, head_w, head_b, out);
}